// round 3
// baseline (speedup 1.0000x reference)
#include <cuda_runtime.h>
#include <math.h>

#define T_  4
#define N_  400
#define S_  395
#define D_  128
#define H0_ 256
#define H1_ 128
#define GD_ 768
#define TNROWS (T_*N_)           // 1600
#define TB  8

// output layout: [wl_mean (400*768)] [learned_score (4*400*400)] [query^T (4*5*400)]
#define OUT_SCORE (N_*GD_)               // 307200
#define OUT_QS    (OUT_SCORE + T_*N_*N_) // 947200

__device__ float g_A[TNROWS*H0_];
__device__ float g_B[TNROWS*H0_];
__device__ float g_support[TNROWS*GD_];
__device__ float g_wl[TNROWS*GD_];
__device__ float g_h2a[TNROWS*H1_];
__device__ float g_h2b[TNROWS*H1_];

__device__ __forceinline__ float sigmoidf_(float x){ return 1.0f/(1.0f + __expf(-x)); }

// ---------------------------------------------------------------------------
// Kernel 1: A[row,h] = nf[row,:]·W1[h,0:128],  B[row,h] = nf[row,:]·W1[h,128:256]
// ---------------------------------------------------------------------------
__global__ void k_precompute(const float* __restrict__ nf, const float* __restrict__ w1)
{
    int row = blockIdx.x;          // t*N_ + n
    int h   = threadIdx.x;         // 0..255
    __shared__ float x[D_];
    if (h < D_) x[h] = nf[row*D_ + h];
    __syncthreads();
    const float* wr = w1 + h*(2*D_);
    float a = 0.f, b = 0.f;
    #pragma unroll 8
    for (int d = 0; d < D_; d++){
        float xv = x[d];
        a += xv * wr[d];
        b += xv * wr[D_ + d];
    }
    g_A[row*H0_ + h] = a;
    g_B[row*H0_ + h] = b;
}

// ---------------------------------------------------------------------------
// Kernel 2: pairwise MLP. One block per (t,a). For every b:
//   h1 = relu(A[a]+B[b]+b1); h2 = relu(W2 h1 + b2); score = sigmoid(w3·h2+b3)
// ---------------------------------------------------------------------------
__global__ void k_pair(const float* __restrict__ b1v, const float* __restrict__ w2,
                       const float* __restrict__ b2v, const float* __restrict__ w3,
                       const float* __restrict__ b3v, float* __restrict__ score_out)
{
    extern __shared__ float sm[];
    float* W2s  = sm;                       // 128 * 257
    float* h1s  = W2s + H1_*257;            // 8 * 256  (16B aligned)
    float* Arow = h1s + TB*H0_;             // 256
    float* b1s  = Arow + H0_;               // 256
    float* red  = b1s + H0_;                // 2*128*8
    float* h2s  = red + 2*H1_*TB;           // 8*128
    float* b2s  = h2s + TB*H1_;             // 128
    float* w3s  = b2s + H1_;                // 128

    int blk = blockIdx.x;                   // t*N_ + a
    int t   = blk / N_;
    int tid = threadIdx.x;

    for (int i = tid; i < H1_*H0_; i += 256){
        int j = i >> 8, k = i & 255;
        W2s[j*257 + k] = w2[i];
    }
    {
        Arow[tid] = g_A[blk*H0_ + tid];
        b1s[tid]  = b1v[tid];
        if (tid < H1_){ b2s[tid] = b2v[tid]; w3s[tid] = w3[tid]; }
    }
    float b3 = b3v[0];

    int kh   = tid >> 7;       // 0/1 : which K-half
    int j    = tid & 127;      // output neuron
    int lane = tid & 31;
    int wrp  = tid >> 5;

    for (int b0 = 0; b0 < N_; b0 += TB){
        __syncthreads();
        // layer 1: fill h1s[bb][k], k = tid
        #pragma unroll
        for (int bb = 0; bb < TB; bb++){
            float v = Arow[tid] + g_B[(t*N_ + b0 + bb)*H0_ + tid] + b1s[tid];
            h1s[bb*H0_ + tid] = fmaxf(v, 0.f);
        }
        __syncthreads();

        // layer 2: each thread computes partial h2[j] over its K-half for 8 b's
        float acc[TB];
        #pragma unroll
        for (int bb = 0; bb < TB; bb++) acc[bb] = 0.f;
        const float* w2r = W2s + j*257;
        for (int k = kh*128; k < kh*128 + 128; k += 4){
            float wa = w2r[k], wb = w2r[k+1], wc = w2r[k+2], wd = w2r[k+3];
            #pragma unroll
            for (int bb = 0; bb < TB; bb++){
                float4 h = *(const float4*)&h1s[bb*H0_ + k];
                acc[bb] += wa*h.x + wb*h.y + wc*h.z + wd*h.w;
            }
        }
        #pragma unroll
        for (int bb = 0; bb < TB; bb++)
            red[(kh*H1_ + j)*TB + bb] = acc[bb];
        __syncthreads();

        // combine halves + bias + relu -> h2s[bb][j]
        #pragma unroll
        for (int i = 0; i < 4; i++){
            int idx = tid*4 + i;               // 0..1023
            int jj  = idx >> 3, bb = idx & 7;
            float v = red[jj*TB + bb] + red[(H1_ + jj)*TB + bb] + b2s[jj];
            h2s[bb*H1_ + jj] = fmaxf(v, 0.f);
        }
        __syncthreads();

        // layer 3: warp w reduces b = b0 + w
        {
            int bb = wrp;
            float p = 0.f;
            #pragma unroll
            for (int i = 0; i < 4; i++){
                int jj = lane + i*32;
                p += h2s[bb*H1_ + jj] * w3s[jj];
            }
            #pragma unroll
            for (int off = 16; off; off >>= 1)
                p += __shfl_xor_sync(0xffffffff, p, off);
            if (lane == 0)
                score_out[blk*N_ + b0 + bb] = sigmoidf_(p + b3);
        }
    }
}

// ---------------------------------------------------------------------------
// Kernel 3: support[m,o] = gcn_in[m,:]·Wg[:,o]   (M=1600, K=768, O=768)
// gcn_in[t,n,f] = f<128 ? nf[t,n,f] : nf[t, S+ (f>>7)-1, f&127]
// ---------------------------------------------------------------------------
__global__ void k_support(const float* __restrict__ nf, const float* __restrict__ Wg)
{
    __shared__ float As[16][64];
    __shared__ float Bs[16][64];
    int tid = threadIdx.x;
    int m0 = blockIdx.y*64, o0 = blockIdx.x*64;
    int tx = tid & 15, ty = tid >> 4;
    float acc[4][4] = {};
    for (int k0 = 0; k0 < GD_; k0 += 16){
        #pragma unroll
        for (int i = 0; i < 4; i++){
            int e = i*256 + tid;
            int r = e >> 4, kk = e & 15;
            int m = m0 + r;
            int tt = m / N_, n = m % N_;
            int f = k0 + kk;
            int node = (f < D_) ? n : (S_ + (f >> 7) - 1);
            As[kk][r] = nf[(tt*N_ + node)*D_ + (f & 127)];
        }
        #pragma unroll
        for (int i = 0; i < 4; i++){
            int e = i*256 + tid;
            int kk = e >> 6, c = e & 63;
            Bs[kk][c] = Wg[(k0 + kk)*GD_ + o0 + c];
        }
        __syncthreads();
        #pragma unroll
        for (int kk = 0; kk < 16; kk++){
            float ra[4], rb[4];
            #pragma unroll
            for (int i = 0; i < 4; i++) ra[i] = As[kk][ty*4 + i];
            #pragma unroll
            for (int jj = 0; jj < 4; jj++) rb[jj] = Bs[kk][tx*4 + jj];
            #pragma unroll
            for (int i = 0; i < 4; i++)
                #pragma unroll
                for (int jj = 0; jj < 4; jj++)
                    acc[i][jj] += ra[i]*rb[jj];
        }
        __syncthreads();
    }
    #pragma unroll
    for (int i = 0; i < 4; i++)
        #pragma unroll
        for (int jj = 0; jj < 4; jj++)
            g_support[(m0 + ty*4 + i)*GD_ + o0 + tx*4 + jj] = acc[i][jj];
}

// ---------------------------------------------------------------------------
// Kernel 4: wl[t,n,o] = relu( sum_m ladj(t,n,m)*support[t,m,o] + biasG[o] )
// ladj on the fly from score + adj. M=400 (guarded), K=400, O=768.
// ---------------------------------------------------------------------------
__global__ void k_wl(const float* __restrict__ adj, const float* __restrict__ score,
                     const float* __restrict__ biasG)
{
    __shared__ float As[16][64];
    __shared__ float Bs[16][64];
    int t = blockIdx.z;
    int tid = threadIdx.x;
    int m0 = blockIdx.y*64, o0 = blockIdx.x*64;
    int tx = tid & 15, ty = tid >> 4;
    float acc[4][4] = {};
    for (int k0 = 0; k0 < N_; k0 += 16){
        #pragma unroll
        for (int i = 0; i < 4; i++){
            int e = i*256 + tid;
            int r = e >> 4, kk = e & 15;
            int n = m0 + r;
            int m = k0 + kk;
            float v = 0.f;
            if (n < N_){
                float sc = score[(t*N_ + n)*N_ + m];
                if (n < S_ && m < S_)
                    v = (adj[(t*S_ + n)*S_ + m] > 0.f) ? 1.f : -sc;
                else
                    v = sc;
            }
            As[kk][r] = v;
        }
        #pragma unroll
        for (int i = 0; i < 4; i++){
            int e = i*256 + tid;
            int kk = e >> 6, c = e & 63;
            Bs[kk][c] = g_support[(t*N_ + k0 + kk)*GD_ + o0 + c];
        }
        __syncthreads();
        #pragma unroll
        for (int kk = 0; kk < 16; kk++){
            float ra[4], rb[4];
            #pragma unroll
            for (int i = 0; i < 4; i++) ra[i] = As[kk][ty*4 + i];
            #pragma unroll
            for (int jj = 0; jj < 4; jj++) rb[jj] = Bs[kk][tx*4 + jj];
            #pragma unroll
            for (int i = 0; i < 4; i++)
                #pragma unroll
                for (int jj = 0; jj < 4; jj++)
                    acc[i][jj] += ra[i]*rb[jj];
        }
        __syncthreads();
    }
    #pragma unroll
    for (int i = 0; i < 4; i++){
        int n = m0 + ty*4 + i;
        if (n < N_){
            #pragma unroll
            for (int jj = 0; jj < 4; jj++){
                int o = o0 + tx*4 + jj;
                g_wl[(t*N_ + n)*GD_ + o] = fmaxf(acc[i][jj] + biasG[o], 0.f);
            }
        }
    }
}

// ---------------------------------------------------------------------------
// Kernel 5: wl mean over t -> out[0 .. 307200)
// ---------------------------------------------------------------------------
__global__ void k_mean(float* __restrict__ out)
{
    int i = blockIdx.x*blockDim.x + threadIdx.x;
    if (i < N_*GD_){
        float s = g_wl[i] + g_wl[i + N_*GD_] + g_wl[i + 2*N_*GD_] + g_wl[i + 3*N_*GD_];
        out[i] = 0.25f * s;
    }
}

// ---------------------------------------------------------------------------
// Kernel 6: h2a[m,o] = relu( wl[m,:]·W1[o,:] + b[o] )   M=1600, K=768, O=128
// ---------------------------------------------------------------------------
__global__ void k_fc2a(const float* __restrict__ W, const float* __restrict__ bias)
{
    __shared__ float As[16][64];
    __shared__ float Bs[16][64];
    int tid = threadIdx.x;
    int m0 = blockIdx.y*64, o0 = blockIdx.x*64;
    int tx = tid & 15, ty = tid >> 4;
    float acc[4][4] = {};
    for (int k0 = 0; k0 < GD_; k0 += 16){
        #pragma unroll
        for (int i = 0; i < 4; i++){
            int e = i*256 + tid;
            int r = e >> 4, kk = e & 15;
            As[kk][r] = g_wl[(m0 + r)*GD_ + k0 + kk];
        }
        {
            int o  = tid >> 2;
            int kq = (tid & 3)*4;
            float4 w = *(const float4*)&W[(o0 + o)*GD_ + k0 + kq];
            Bs[kq+0][o] = w.x; Bs[kq+1][o] = w.y; Bs[kq+2][o] = w.z; Bs[kq+3][o] = w.w;
        }
        __syncthreads();
        #pragma unroll
        for (int kk = 0; kk < 16; kk++){
            float ra[4], rb[4];
            #pragma unroll
            for (int i = 0; i < 4; i++) ra[i] = As[kk][ty*4 + i];
            #pragma unroll
            for (int jj = 0; jj < 4; jj++) rb[jj] = Bs[kk][tx*4 + jj];
            #pragma unroll
            for (int i = 0; i < 4; i++)
                #pragma unroll
                for (int jj = 0; jj < 4; jj++)
                    acc[i][jj] += ra[i]*rb[jj];
        }
        __syncthreads();
    }
    #pragma unroll
    for (int i = 0; i < 4; i++)
        #pragma unroll
        for (int jj = 0; jj < 4; jj++){
            int o = o0 + tx*4 + jj;
            g_h2a[(m0 + ty*4 + i)*H1_ + o] = fmaxf(acc[i][jj] + bias[o], 0.f);
        }
}

// ---------------------------------------------------------------------------
// Kernel 7: h2b[m,o] = relu( h2a[m,:]·W2[o,:] + b[o] )   M=1600, K=128, O=128
// ---------------------------------------------------------------------------
__global__ void k_fc2b(const float* __restrict__ W, const float* __restrict__ bias)
{
    __shared__ float As[16][64];
    __shared__ float Bs[16][64];
    int tid = threadIdx.x;
    int m0 = blockIdx.y*64, o0 = blockIdx.x*64;
    int tx = tid & 15, ty = tid >> 4;
    float acc[4][4] = {};
    for (int k0 = 0; k0 < H1_; k0 += 16){
        #pragma unroll
        for (int i = 0; i < 4; i++){
            int e = i*256 + tid;
            int r = e >> 4, kk = e & 15;
            As[kk][r] = g_h2a[(m0 + r)*H1_ + k0 + kk];
        }
        {
            int o  = tid >> 2;
            int kq = (tid & 3)*4;
            float4 w = *(const float4*)&W[(o0 + o)*H1_ + k0 + kq];
            Bs[kq+0][o] = w.x; Bs[kq+1][o] = w.y; Bs[kq+2][o] = w.z; Bs[kq+3][o] = w.w;
        }
        __syncthreads();
        #pragma unroll
        for (int kk = 0; kk < 16; kk++){
            float ra[4], rb[4];
            #pragma unroll
            for (int i = 0; i < 4; i++) ra[i] = As[kk][ty*4 + i];
            #pragma unroll
            for (int jj = 0; jj < 4; jj++) rb[jj] = Bs[kk][tx*4 + jj];
            #pragma unroll
            for (int i = 0; i < 4; i++)
                #pragma unroll
                for (int jj = 0; jj < 4; jj++)
                    acc[i][jj] += ra[i]*rb[jj];
        }
        __syncthreads();
    }
    #pragma unroll
    for (int i = 0; i < 4; i++)
        #pragma unroll
        for (int jj = 0; jj < 4; jj++){
            int o = o0 + tx*4 + jj;
            g_h2b[(m0 + ty*4 + i)*H1_ + o] = fmaxf(acc[i][jj] + bias[o], 0.f);
        }
}

// ---------------------------------------------------------------------------
// Kernel 8: query[t,c,n] = sigmoid( h2b[t,n,:]·w3[c,:] + b3[c] )
// ---------------------------------------------------------------------------
__global__ void k_query(const float* __restrict__ w3, const float* __restrict__ b3,
                        float* __restrict__ out)
{
    int idx = blockIdx.x*blockDim.x + threadIdx.x;
    if (idx >= TNROWS*5) return;
    int row = idx / 5, c = idx % 5;
    const float* h = g_h2b + row*H1_;
    const float* w = w3 + c*H1_;
    float s = 0.f;
    #pragma unroll 8
    for (int k = 0; k < H1_; k++) s += h[k]*w[k];
    int t = row / N_, n = row % N_;
    out[OUT_QS + t*5*N_ + c*N_ + n] = sigmoidf_(s + b3[c]);
}

// ---------------------------------------------------------------------------
extern "C" void kernel_launch(void* const* d_in, const int* in_sizes, int n_in,
                              void* d_out, int out_size)
{
    const float* nf       = (const float*)d_in[0];
    const float* adj      = (const float*)d_in[1];
    const float* fc1_w1   = (const float*)d_in[2];
    const float* fc1_b1   = (const float*)d_in[3];
    const float* fc1_w2   = (const float*)d_in[4];
    const float* fc1_b2   = (const float*)d_in[5];
    const float* fc1_w3   = (const float*)d_in[6];
    const float* fc1_b3   = (const float*)d_in[7];
    const float* weight_G = (const float*)d_in[8];
    const float* bias_G   = (const float*)d_in[9];
    const float* fc2_w1   = (const float*)d_in[10];
    const float* fc2_b1   = (const float*)d_in[11];
    const float* fc2_w2   = (const float*)d_in[12];
    const float* fc2_b2   = (const float*)d_in[13];
    const float* fc2_w3   = (const float*)d_in[14];
    const float* fc2_b3   = (const float*)d_in[15];

    float* out       = (float*)d_out;
    float* score_out = out + OUT_SCORE;

    size_t smem_pair = (size_t)(H1_*257 + TB*H0_ + H0_ + H0_ + 2*H1_*TB + TB*H1_ + H1_ + H1_) * sizeof(float);
    cudaFuncSetAttribute(k_pair, cudaFuncAttributeMaxDynamicSharedMemorySize, (int)smem_pair);

    k_precompute<<<TNROWS, 256>>>(nf, fc1_w1);
    k_pair<<<TNROWS, 256, smem_pair>>>(fc1_b1, fc1_w2, fc1_b2, fc1_w3, fc1_b3, score_out);
    k_support<<<dim3(GD_/64, TNROWS/64), 256>>>(nf, weight_G);
    k_wl<<<dim3(GD_/64, (N_ + 63)/64, T_), 256>>>(adj, score_out, bias_G);
    k_mean<<<(N_*GD_ + 255)/256, 256>>>(out);
    k_fc2a<<<dim3(H1_/64, TNROWS/64), 256>>>(fc2_w1, fc2_b1);
    k_fc2b<<<dim3(H1_/64, TNROWS/64), 256>>>(fc2_w2, fc2_b2);
    k_query<<<(TNROWS*5 + 127)/128, 128>>>(fc2_w3, fc2_b3, out);
}

// round 4
// speedup vs baseline: 1.0004x; 1.0004x over previous
#include <cuda_runtime.h>
#include <math.h>

#define T_  4
#define N_  400
#define S_  395
#define D_  128
#define H0_ 256
#define H1_ 128
#define GD_ 768
#define TNROWS (T_*N_)           // 1600
#define TB  8

// output layout: [wl_mean (400*768)] [learned_score (4*400*400)] [query^T (4*5*400)]
#define OUT_SCORE (N_*GD_)               // 307200
#define OUT_QS    (OUT_SCORE + T_*N_*N_) // 947200

__device__ float g_A[TNROWS*H0_];
__device__ float g_B[TNROWS*H0_];
__device__ float g_support[TNROWS*GD_];
__device__ float g_wl[TNROWS*GD_];
__device__ float g_h2a[TNROWS*H1_];
__device__ float g_h2b[TNROWS*H1_];

__device__ __forceinline__ float sigmoidf_(float x){ return 1.0f/(1.0f + __expf(-x)); }

// ---------------------------------------------------------------------------
// Kernel 1: A[row,h] = nf[row,:]·W1[h,0:128],  B[row,h] = nf[row,:]·W1[h,128:256]
// ---------------------------------------------------------------------------
__global__ void k_precompute(const float* __restrict__ nf, const float* __restrict__ w1)
{
    int row = blockIdx.x;          // t*N_ + n
    int h   = threadIdx.x;         // 0..255
    __shared__ float x[D_];
    if (h < D_) x[h] = nf[row*D_ + h];
    __syncthreads();
    const float* wr = w1 + h*(2*D_);
    float a = 0.f, b = 0.f;
    #pragma unroll 8
    for (int d = 0; d < D_; d++){
        float xv = x[d];
        a += xv * wr[d];
        b += xv * wr[D_ + d];
    }
    g_A[row*H0_ + h] = a;
    g_B[row*H0_ + h] = b;
}

// ---------------------------------------------------------------------------
// Kernel 2: pairwise MLP. One block per (t,a). For every b:
//   h1 = relu(A[a]+B[b]+b1); h2 = relu(W2 h1 + b2); score = sigmoid(w3·h2+b3)
// ---------------------------------------------------------------------------
__global__ void k_pair(const float* __restrict__ b1v, const float* __restrict__ w2,
                       const float* __restrict__ b2v, const float* __restrict__ w3,
                       const float* __restrict__ b3v, float* __restrict__ score_out)
{
    extern __shared__ float sm[];
    float* W2s  = sm;                       // 128 * 257
    float* h1s  = W2s + H1_*257;            // 8 * 256  (16B aligned)
    float* Arow = h1s + TB*H0_;             // 256
    float* b1s  = Arow + H0_;               // 256
    float* red  = b1s + H0_;                // 2*128*8
    float* h2s  = red + 2*H1_*TB;           // 8*128
    float* b2s  = h2s + TB*H1_;             // 128
    float* w3s  = b2s + H1_;                // 128

    int blk = blockIdx.x;                   // t*N_ + a
    int t   = blk / N_;
    int tid = threadIdx.x;

    for (int i = tid; i < H1_*H0_; i += 256){
        int j = i >> 8, k = i & 255;
        W2s[j*257 + k] = w2[i];
    }
    {
        Arow[tid] = g_A[blk*H0_ + tid];
        b1s[tid]  = b1v[tid];
        if (tid < H1_){ b2s[tid] = b2v[tid]; w3s[tid] = w3[tid]; }
    }
    float b3 = b3v[0];

    int kh   = tid >> 7;       // 0/1 : which K-half
    int j    = tid & 127;      // output neuron
    int lane = tid & 31;
    int wrp  = tid >> 5;

    for (int b0 = 0; b0 < N_; b0 += TB){
        __syncthreads();
        // layer 1: fill h1s[bb][k], k = tid
        #pragma unroll
        for (int bb = 0; bb < TB; bb++){
            float v = Arow[tid] + g_B[(t*N_ + b0 + bb)*H0_ + tid] + b1s[tid];
            h1s[bb*H0_ + tid] = fmaxf(v, 0.f);
        }
        __syncthreads();

        // layer 2: each thread computes partial h2[j] over its K-half for 8 b's
        float acc[TB];
        #pragma unroll
        for (int bb = 0; bb < TB; bb++) acc[bb] = 0.f;
        const float* w2r = W2s + j*257;
        for (int k = kh*128; k < kh*128 + 128; k += 4){
            float wa = w2r[k], wb = w2r[k+1], wc = w2r[k+2], wd = w2r[k+3];
            #pragma unroll
            for (int bb = 0; bb < TB; bb++){
                float4 h = *(const float4*)&h1s[bb*H0_ + k];
                acc[bb] += wa*h.x + wb*h.y + wc*h.z + wd*h.w;
            }
        }
        #pragma unroll
        for (int bb = 0; bb < TB; bb++)
            red[(kh*H1_ + j)*TB + bb] = acc[bb];
        __syncthreads();

        // combine halves + bias + relu -> h2s[bb][j]
        #pragma unroll
        for (int i = 0; i < 4; i++){
            int idx = tid*4 + i;               // 0..1023
            int jj  = idx >> 3, bb = idx & 7;
            float v = red[jj*TB + bb] + red[(H1_ + jj)*TB + bb] + b2s[jj];
            h2s[bb*H1_ + jj] = fmaxf(v, 0.f);
        }
        __syncthreads();

        // layer 3: warp w reduces b = b0 + w
        {
            int bb = wrp;
            float p = 0.f;
            #pragma unroll
            for (int i = 0; i < 4; i++){
                int jj = lane + i*32;
                p += h2s[bb*H1_ + jj] * w3s[jj];
            }
            #pragma unroll
            for (int off = 16; off; off >>= 1)
                p += __shfl_xor_sync(0xffffffff, p, off);
            if (lane == 0)
                score_out[blk*N_ + b0 + bb] = sigmoidf_(p + b3);
        }
    }
}

// ---------------------------------------------------------------------------
// Kernel 3: support[m,o] = gcn_in[m,:]·Wg[:,o]   (M=1600, K=768, O=768)
// gcn_in[t,n,f] = f<128 ? nf[t,n,f] : nf[t, S+ (f>>7)-1, f&127]
// ---------------------------------------------------------------------------
__global__ void k_support(const float* __restrict__ nf, const float* __restrict__ Wg)
{
    __shared__ float As[16][64];
    __shared__ float Bs[16][64];
    int tid = threadIdx.x;
    int m0 = blockIdx.y*64, o0 = blockIdx.x*64;
    int tx = tid & 15, ty = tid >> 4;
    float acc[4][4] = {};
    for (int k0 = 0; k0 < GD_; k0 += 16){
        #pragma unroll
        for (int i = 0; i < 4; i++){
            int e = i*256 + tid;
            int r = e >> 4, kk = e & 15;
            int m = m0 + r;
            int tt = m / N_, n = m % N_;
            int f = k0 + kk;
            int node = (f < D_) ? n : (S_ + (f >> 7) - 1);
            As[kk][r] = nf[(tt*N_ + node)*D_ + (f & 127)];
        }
        #pragma unroll
        for (int i = 0; i < 4; i++){
            int e = i*256 + tid;
            int kk = e >> 6, c = e & 63;
            Bs[kk][c] = Wg[(k0 + kk)*GD_ + o0 + c];
        }
        __syncthreads();
        #pragma unroll
        for (int kk = 0; kk < 16; kk++){
            float ra[4], rb[4];
            #pragma unroll
            for (int i = 0; i < 4; i++) ra[i] = As[kk][ty*4 + i];
            #pragma unroll
            for (int jj = 0; jj < 4; jj++) rb[jj] = Bs[kk][tx*4 + jj];
            #pragma unroll
            for (int i = 0; i < 4; i++)
                #pragma unroll
                for (int jj = 0; jj < 4; jj++)
                    acc[i][jj] += ra[i]*rb[jj];
        }
        __syncthreads();
    }
    #pragma unroll
    for (int i = 0; i < 4; i++)
        #pragma unroll
        for (int jj = 0; jj < 4; jj++)
            g_support[(m0 + ty*4 + i)*GD_ + o0 + tx*4 + jj] = acc[i][jj];
}

// ---------------------------------------------------------------------------
// Kernel 4: wl[t,n,o] = relu( sum_m ladj(t,n,m)*support[t,m,o] + biasG[o] )
// ladj on the fly from score + adj. M=400 (guarded), K=400, O=768.
// ---------------------------------------------------------------------------
__global__ void k_wl(const float* __restrict__ adj, const float* __restrict__ score,
                     const float* __restrict__ biasG)
{
    __shared__ float As[16][64];
    __shared__ float Bs[16][64];
    int t = blockIdx.z;
    int tid = threadIdx.x;
    int m0 = blockIdx.y*64, o0 = blockIdx.x*64;
    int tx = tid & 15, ty = tid >> 4;
    float acc[4][4] = {};
    for (int k0 = 0; k0 < N_; k0 += 16){
        #pragma unroll
        for (int i = 0; i < 4; i++){
            int e = i*256 + tid;
            int r = e >> 4, kk = e & 15;
            int n = m0 + r;
            int m = k0 + kk;
            float v = 0.f;
            if (n < N_){
                float sc = score[(t*N_ + n)*N_ + m];
                if (n < S_ && m < S_)
                    v = (adj[(t*S_ + n)*S_ + m] > 0.f) ? 1.f : -sc;
                else
                    v = sc;
            }
            As[kk][r] = v;
        }
        #pragma unroll
        for (int i = 0; i < 4; i++){
            int e = i*256 + tid;
            int kk = e >> 6, c = e & 63;
            Bs[kk][c] = g_support[(t*N_ + k0 + kk)*GD_ + o0 + c];
        }
        __syncthreads();
        #pragma unroll
        for (int kk = 0; kk < 16; kk++){
            float ra[4], rb[4];
            #pragma unroll
            for (int i = 0; i < 4; i++) ra[i] = As[kk][ty*4 + i];
            #pragma unroll
            for (int jj = 0; jj < 4; jj++) rb[jj] = Bs[kk][tx*4 + jj];
            #pragma unroll
            for (int i = 0; i < 4; i++)
                #pragma unroll
                for (int jj = 0; jj < 4; jj++)
                    acc[i][jj] += ra[i]*rb[jj];
        }
        __syncthreads();
    }
    #pragma unroll
    for (int i = 0; i < 4; i++){
        int n = m0 + ty*4 + i;
        if (n < N_){
            #pragma unroll
            for (int jj = 0; jj < 4; jj++){
                int o = o0 + tx*4 + jj;
                g_wl[(t*N_ + n)*GD_ + o] = fmaxf(acc[i][jj] + biasG[o], 0.f);
            }
        }
    }
}

// ---------------------------------------------------------------------------
// Kernel 5: wl mean over t -> out[0 .. 307200)
// ---------------------------------------------------------------------------
__global__ void k_mean(float* __restrict__ out)
{
    int i = blockIdx.x*blockDim.x + threadIdx.x;
    if (i < N_*GD_){
        float s = g_wl[i] + g_wl[i + N_*GD_] + g_wl[i + 2*N_*GD_] + g_wl[i + 3*N_*GD_];
        out[i] = 0.25f * s;
    }
}

// ---------------------------------------------------------------------------
// Kernel 6: h2a[m,o] = relu( wl[m,:]·W1[o,:] + b[o] )   M=1600, K=768, O=128
// ---------------------------------------------------------------------------
__global__ void k_fc2a(const float* __restrict__ W, const float* __restrict__ bias)
{
    __shared__ float As[16][64];
    __shared__ float Bs[16][64];
    int tid = threadIdx.x;
    int m0 = blockIdx.y*64, o0 = blockIdx.x*64;
    int tx = tid & 15, ty = tid >> 4;
    float acc[4][4] = {};
    for (int k0 = 0; k0 < GD_; k0 += 16){
        #pragma unroll
        for (int i = 0; i < 4; i++){
            int e = i*256 + tid;
            int r = e >> 4, kk = e & 15;
            As[kk][r] = g_wl[(m0 + r)*GD_ + k0 + kk];
        }
        {
            int o  = tid >> 2;
            int kq = (tid & 3)*4;
            float4 w = *(const float4*)&W[(o0 + o)*GD_ + k0 + kq];
            Bs[kq+0][o] = w.x; Bs[kq+1][o] = w.y; Bs[kq+2][o] = w.z; Bs[kq+3][o] = w.w;
        }
        __syncthreads();
        #pragma unroll
        for (int kk = 0; kk < 16; kk++){
            float ra[4], rb[4];
            #pragma unroll
            for (int i = 0; i < 4; i++) ra[i] = As[kk][ty*4 + i];
            #pragma unroll
            for (int jj = 0; jj < 4; jj++) rb[jj] = Bs[kk][tx*4 + jj];
            #pragma unroll
            for (int i = 0; i < 4; i++)
                #pragma unroll
                for (int jj = 0; jj < 4; jj++)
                    acc[i][jj] += ra[i]*rb[jj];
        }
        __syncthreads();
    }
    #pragma unroll
    for (int i = 0; i < 4; i++)
        #pragma unroll
        for (int jj = 0; jj < 4; jj++){
            int o = o0 + tx*4 + jj;
            g_h2a[(m0 + ty*4 + i)*H1_ + o] = fmaxf(acc[i][jj] + bias[o], 0.f);
        }
}

// ---------------------------------------------------------------------------
// Kernel 7: h2b[m,o] = relu( h2a[m,:]·W2[o,:] + b[o] )   M=1600, K=128, O=128
// ---------------------------------------------------------------------------
__global__ void k_fc2b(const float* __restrict__ W, const float* __restrict__ bias)
{
    __shared__ float As[16][64];
    __shared__ float Bs[16][64];
    int tid = threadIdx.x;
    int m0 = blockIdx.y*64, o0 = blockIdx.x*64;
    int tx = tid & 15, ty = tid >> 4;
    float acc[4][4] = {};
    for (int k0 = 0; k0 < H1_; k0 += 16){
        #pragma unroll
        for (int i = 0; i < 4; i++){
            int e = i*256 + tid;
            int r = e >> 4, kk = e & 15;
            As[kk][r] = g_h2a[(m0 + r)*H1_ + k0 + kk];
        }
        {
            int o  = tid >> 2;
            int kq = (tid & 3)*4;
            float4 w = *(const float4*)&W[(o0 + o)*H1_ + k0 + kq];
            Bs[kq+0][o] = w.x; Bs[kq+1][o] = w.y; Bs[kq+2][o] = w.z; Bs[kq+3][o] = w.w;
        }
        __syncthreads();
        #pragma unroll
        for (int kk = 0; kk < 16; kk++){
            float ra[4], rb[4];
            #pragma unroll
            for (int i = 0; i < 4; i++) ra[i] = As[kk][ty*4 + i];
            #pragma unroll
            for (int jj = 0; jj < 4; jj++) rb[jj] = Bs[kk][tx*4 + jj];
            #pragma unroll
            for (int i = 0; i < 4; i++)
                #pragma unroll
                for (int jj = 0; jj < 4; jj++)
                    acc[i][jj] += ra[i]*rb[jj];
        }
        __syncthreads();
    }
    #pragma unroll
    for (int i = 0; i < 4; i++)
        #pragma unroll
        for (int jj = 0; jj < 4; jj++){
            int o = o0 + tx*4 + jj;
            g_h2b[(m0 + ty*4 + i)*H1_ + o] = fmaxf(acc[i][jj] + bias[o], 0.f);
        }
}

// ---------------------------------------------------------------------------
// Kernel 8: query[t,c,n] = sigmoid( h2b[t,n,:]·w3[c,:] + b3[c] )
// ---------------------------------------------------------------------------
__global__ void k_query(const float* __restrict__ w3, const float* __restrict__ b3,
                        float* __restrict__ out)
{
    int idx = blockIdx.x*blockDim.x + threadIdx.x;
    if (idx >= TNROWS*5) return;
    int row = idx / 5, c = idx % 5;
    const float* h = g_h2b + row*H1_;
    const float* w = w3 + c*H1_;
    float s = 0.f;
    #pragma unroll 8
    for (int k = 0; k < H1_; k++) s += h[k]*w[k];
    int t = row / N_, n = row % N_;
    out[OUT_QS + t*5*N_ + c*N_ + n] = sigmoidf_(s + b3[c]);
}

// ---------------------------------------------------------------------------
extern "C" void kernel_launch(void* const* d_in, const int* in_sizes, int n_in,
                              void* d_out, int out_size)
{
    const float* nf       = (const float*)d_in[0];
    const float* adj      = (const float*)d_in[1];
    const float* fc1_w1   = (const float*)d_in[2];
    const float* fc1_b1   = (const float*)d_in[3];
    const float* fc1_w2   = (const float*)d_in[4];
    const float* fc1_b2   = (const float*)d_in[5];
    const float* fc1_w3   = (const float*)d_in[6];
    const float* fc1_b3   = (const float*)d_in[7];
    const float* weight_G = (const float*)d_in[8];
    const float* bias_G   = (const float*)d_in[9];
    const float* fc2_w1   = (const float*)d_in[10];
    const float* fc2_b1   = (const float*)d_in[11];
    const float* fc2_w2   = (const float*)d_in[12];
    const float* fc2_b2   = (const float*)d_in[13];
    const float* fc2_w3   = (const float*)d_in[14];
    const float* fc2_b3   = (const float*)d_in[15];

    float* out       = (float*)d_out;
    float* score_out = out + OUT_SCORE;

    size_t smem_pair = (size_t)(H1_*257 + TB*H0_ + H0_ + H0_ + 2*H1_*TB + TB*H1_ + H1_ + H1_) * sizeof(float);
    cudaFuncSetAttribute(k_pair, cudaFuncAttributeMaxDynamicSharedMemorySize, (int)smem_pair);

    k_precompute<<<TNROWS, 256>>>(nf, fc1_w1);
    k_pair<<<TNROWS, 256, smem_pair>>>(fc1_b1, fc1_w2, fc1_b2, fc1_w3, fc1_b3, score_out);
    k_support<<<dim3(GD_/64, TNROWS/64), 256>>>(nf, weight_G);
    k_wl<<<dim3(GD_/64, (N_ + 63)/64, T_), 256>>>(adj, score_out, bias_G);
    k_mean<<<(N_*GD_ + 255)/256, 256>>>(out);
    k_fc2a<<<dim3(H1_/64, TNROWS/64), 256>>>(fc2_w1, fc2_b1);
    k_fc2b<<<dim3(H1_/64, TNROWS/64), 256>>>(fc2_w2, fc2_b2);
    k_query<<<(TNROWS*5 + 127)/128, 128>>>(fc2_w3, fc2_b3, out);
}

// round 5
// speedup vs baseline: 6.1786x; 6.1760x over previous
#include <cuda_runtime.h>
#include <cuda_fp16.h>
#include <math.h>

#define T_  4
#define N_  400
#define S_  395
#define D_  128
#define H0_ 256
#define H1_ 128
#define GD_ 768
#define TNROWS (T_*N_)           // 1600

// output layout: [wl_mean (400*768)] [learned_score (4*400*400)] [query^T (4*5*400)]
#define OUT_SCORE (N_*GD_)               // 307200
#define OUT_QS    (OUT_SCORE + T_*N_*N_) // 947200

#define ROWH 264                 // padded half-row stride for ldmatrix tiles

__device__ float g_A[TNROWS*H0_];
__device__ float g_B[TNROWS*H0_];
__device__ float g_support[TNROWS*GD_];
__device__ float g_wl[TNROWS*GD_];
__device__ float g_h2a[TNROWS*H1_];
__device__ float g_h2b[TNROWS*H1_];

__device__ __forceinline__ float sigmoidf_(float x){ return 1.0f/(1.0f + __expf(-x)); }

__device__ __forceinline__ void ldsm_x4(unsigned* r, unsigned addr){
    asm volatile("ldmatrix.sync.aligned.m8n8.x4.shared.b16 {%0,%1,%2,%3}, [%4];"
        : "=r"(r[0]), "=r"(r[1]), "=r"(r[2]), "=r"(r[3]) : "r"(addr));
}
__device__ __forceinline__ void mma16816(float* d, const unsigned* a, const unsigned* b){
    asm volatile("mma.sync.aligned.m16n8k16.row.col.f32.f16.f16.f32 "
        "{%0,%1,%2,%3},{%4,%5,%6,%7},{%8,%9},{%0,%1,%2,%3};"
        : "+f"(d[0]), "+f"(d[1]), "+f"(d[2]), "+f"(d[3])
        : "r"(a[0]), "r"(a[1]), "r"(a[2]), "r"(a[3]), "r"(b[0]), "r"(b[1]));
}

// ---------------------------------------------------------------------------
// Kernel 1 (GEMM form): out[m, h'] = nf[m,:]·W1c[h',:]  for h' in [0,512)
//   W1c[h'][d] = w1[(h'&255)*256 + (h'>>8)*128 + d];  h'<256 -> g_A, else g_B
// ---------------------------------------------------------------------------
__global__ void k_pre(const float* __restrict__ nf, const float* __restrict__ w1)
{
    __shared__ float As[16][64];
    __shared__ float Bs[16][64];
    int tid = threadIdx.x;
    int m0 = blockIdx.y*64, h0 = blockIdx.x*64;
    int tx = tid & 15, ty = tid >> 4;
    float acc[4][4] = {};
    for (int k0 = 0; k0 < D_; k0 += 16){
        #pragma unroll
        for (int i = 0; i < 4; i++){
            int e = i*256 + tid;
            int r = e >> 4, kk = e & 15;
            int m = m0 + r;
            As[kk][r] = nf[m*D_ + k0 + kk];
        }
        {
            int o  = tid >> 2;
            int kq = (tid & 3)*4;
            int hp = h0 + o;
            const float* src = w1 + (hp & 255)*(2*D_) + (hp >> 8)*D_ + k0 + kq;
            float4 w = *(const float4*)src;
            Bs[kq+0][o] = w.x; Bs[kq+1][o] = w.y; Bs[kq+2][o] = w.z; Bs[kq+3][o] = w.w;
        }
        __syncthreads();
        #pragma unroll
        for (int kk = 0; kk < 16; kk++){
            float ra[4], rb[4];
            #pragma unroll
            for (int i = 0; i < 4; i++) ra[i] = As[kk][ty*4 + i];
            #pragma unroll
            for (int jj = 0; jj < 4; jj++) rb[jj] = Bs[kk][tx*4 + jj];
            #pragma unroll
            for (int i = 0; i < 4; i++)
                #pragma unroll
                for (int jj = 0; jj < 4; jj++)
                    acc[i][jj] += ra[i]*rb[jj];
        }
        __syncthreads();
    }
    #pragma unroll
    for (int i = 0; i < 4; i++)
        #pragma unroll
        for (int jj = 0; jj < 4; jj++){
            int hp = h0 + tx*4 + jj;
            float* dst = (hp < H0_) ? g_A : g_B;
            dst[(m0 + ty*4 + i)*H0_ + (hp & 255)] = acc[i][jj];
        }
}

// ---------------------------------------------------------------------------
// Kernel 2: pairwise MLP via fp16 tensor-core GEMM.
// One block per (t,a). P[b,j] = relu(A[a]+B[b]+b1) · W2[j,:], b-tiles of 128.
// ---------------------------------------------------------------------------
__global__ void __launch_bounds__(256, 1)
k_pair(const float* __restrict__ b1v, const float* __restrict__ w2,
       const float* __restrict__ b2v, const float* __restrict__ w3,
       const float* __restrict__ b3v, float* __restrict__ score_out)
{
    extern __shared__ char smraw[];
    __half* h1s  = (__half*)smraw;                    // 128 * 264
    __half* W2s  = h1s + 128*ROWH;                    // 128 * 264
    float*  Arb1 = (float*)(W2s + 128*ROWH);          // 256
    float*  sred = Arb1 + H0_;                        // 128
    float*  b2s  = sred + H1_;                        // 128
    float*  w3s  = b2s + H1_;                         // 128

    int blk  = blockIdx.x;                            // t*N_ + a
    int t    = blk / N_;
    int tid  = threadIdx.x;
    int lane = tid & 31;
    int wid  = tid >> 5;
    int warp_n = wid & 3;                             // 0..3 (j chunks of 32)
    int warp_m = wid >> 2;                            // 0..1 (b chunks of 64)

    // stage W2 (fp32 -> fp16), A-row + b1, b2, w3
    for (int idx = tid; idx < 128*64; idx += 256){
        int row = idx >> 6, c4 = idx & 63;
        float4 w = *(const float4*)&w2[row*H0_ + c4*4];
        __half2 lo = __floats2half2_rn(w.x, w.y);
        __half2 hi = __floats2half2_rn(w.z, w.w);
        *(__half2*)&W2s[row*ROWH + c4*4]     = lo;
        *(__half2*)&W2s[row*ROWH + c4*4 + 2] = hi;
    }
    Arb1[tid] = g_A[blk*H0_ + tid] + b1v[tid];
    if (tid < H1_){ b2s[tid] = b2v[tid]; w3s[tid] = w3[tid]; }
    float b3 = b3v[0];

    unsigned h1u = (unsigned)__cvta_generic_to_shared(h1s);
    unsigned w2u = (unsigned)__cvta_generic_to_shared(W2s);

    // ldmatrix lane address pieces
    int a_trow  = lane & 15;
    int a_tcol8 = (lane >> 4) * 8;
    int b_g     = lane >> 3;
    int b_i     = lane & 7;
    int b_joff  = ((b_g >= 2) ? 8 : 0) + b_i;
    int b_koff  = (b_g & 1) * 8;

    for (int b0 = 0; b0 < N_; b0 += 128){
        __syncthreads();
        // stage h1 tile: 128 rows x 256 halves; zero score reduction
        for (int idx = tid; idx < 128*64; idx += 256){
            int row = idx >> 6, c4 = idx & 63;
            int bg = b0 + row;
            float4 v;
            if (bg < N_) v = *(const float4*)&g_B[((t*N_ + bg)*H0_) + c4*4];
            else         v = make_float4(0.f,0.f,0.f,0.f);
            float h0f = fmaxf(v.x + Arb1[c4*4+0], 0.f);
            float h1f = fmaxf(v.y + Arb1[c4*4+1], 0.f);
            float h2f = fmaxf(v.z + Arb1[c4*4+2], 0.f);
            float h3f = fmaxf(v.w + Arb1[c4*4+3], 0.f);
            *(__half2*)&h1s[row*ROWH + c4*4]     = __floats2half2_rn(h0f, h1f);
            *(__half2*)&h1s[row*ROWH + c4*4 + 2] = __floats2half2_rn(h2f, h3f);
        }
        if (tid < H1_) sred[tid] = 0.f;
        __syncthreads();

        // mainloop: warp tile m64 x n32, K=256 in 16-steps
        float d[4][4][4];
        #pragma unroll
        for (int i=0;i<4;i++) for (int j=0;j<4;j++) for (int v=0;v<4;v++) d[i][j][v]=0.f;

        unsigned aA[4], bA[2];
        #pragma unroll
        for (int mt = 0; mt < 4; mt++)
            aA[mt] = h1u + ((warp_m*64 + mt*16 + a_trow)*ROWH + a_tcol8)*2;
        #pragma unroll
        for (int nb = 0; nb < 2; nb++)
            bA[nb] = w2u + ((warp_n*32 + nb*16 + b_joff)*ROWH + b_koff)*2;

        for (int ks = 0; ks < 16; ks++){
            unsigned a[4][4], b[2][4];
            #pragma unroll
            for (int mt = 0; mt < 4; mt++) ldsm_x4(a[mt], aA[mt] + ks*32);
            #pragma unroll
            for (int nb = 0; nb < 2; nb++) ldsm_x4(b[nb], bA[nb] + ks*32);
            #pragma unroll
            for (int mt = 0; mt < 4; mt++){
                #pragma unroll
                for (int nb = 0; nb < 2; nb++){
                    mma16816(d[mt][nb*2+0], a[mt], &b[nb][0]);
                    mma16816(d[mt][nb*2+1], a[mt], &b[nb][2]);
                }
            }
        }

        // epilogue: h2 = relu(P + b2); partial = h2·w3 over this warp's n32
        #pragma unroll
        for (int mt = 0; mt < 4; mt++){
            #pragma unroll
            for (int h = 0; h < 2; h++){
                float part = 0.f;
                #pragma unroll
                for (int n8 = 0; n8 < 4; n8++){
                    #pragma unroll
                    for (int c = 0; c < 2; c++){
                        int j = warp_n*32 + n8*8 + (lane & 3)*2 + c;
                        float val = d[mt][n8][h*2 + c] + b2s[j];
                        part += fmaxf(val, 0.f) * w3s[j];
                    }
                }
                part += __shfl_xor_sync(0xffffffff, part, 1);
                part += __shfl_xor_sync(0xffffffff, part, 2);
                if ((lane & 3) == 0){
                    int row = warp_m*64 + mt*16 + (lane >> 2) + h*8;
                    atomicAdd(&sred[row], part);
                }
            }
        }
        __syncthreads();

        if (tid < H1_){
            int bg = b0 + tid;
            if (bg < N_)
                score_out[blk*N_ + bg] = sigmoidf_(sred[tid] + b3);
        }
    }
}

// ---------------------------------------------------------------------------
// Kernel 3: support[m,o] = gcn_in[m,:]·Wg[:,o]   (M=1600, K=768, O=768)
// ---------------------------------------------------------------------------
__global__ void k_support(const float* __restrict__ nf, const float* __restrict__ Wg)
{
    __shared__ float As[16][64];
    __shared__ float Bs[16][64];
    int tid = threadIdx.x;
    int m0 = blockIdx.y*64, o0 = blockIdx.x*64;
    int tx = tid & 15, ty = tid >> 4;
    float acc[4][4] = {};
    for (int k0 = 0; k0 < GD_; k0 += 16){
        #pragma unroll
        for (int i = 0; i < 4; i++){
            int e = i*256 + tid;
            int r = e >> 4, kk = e & 15;
            int m = m0 + r;
            int tt = m / N_, n = m % N_;
            int f = k0 + kk;
            int node = (f < D_) ? n : (S_ + (f >> 7) - 1);
            As[kk][r] = nf[(tt*N_ + node)*D_ + (f & 127)];
        }
        #pragma unroll
        for (int i = 0; i < 4; i++){
            int e = i*256 + tid;
            int kk = e >> 6, c = e & 63;
            Bs[kk][c] = Wg[(k0 + kk)*GD_ + o0 + c];
        }
        __syncthreads();
        #pragma unroll
        for (int kk = 0; kk < 16; kk++){
            float ra[4], rb[4];
            #pragma unroll
            for (int i = 0; i < 4; i++) ra[i] = As[kk][ty*4 + i];
            #pragma unroll
            for (int jj = 0; jj < 4; jj++) rb[jj] = Bs[kk][tx*4 + jj];
            #pragma unroll
            for (int i = 0; i < 4; i++)
                #pragma unroll
                for (int jj = 0; jj < 4; jj++)
                    acc[i][jj] += ra[i]*rb[jj];
        }
        __syncthreads();
    }
    #pragma unroll
    for (int i = 0; i < 4; i++)
        #pragma unroll
        for (int jj = 0; jj < 4; jj++)
            g_support[(m0 + ty*4 + i)*GD_ + o0 + tx*4 + jj] = acc[i][jj];
}

// ---------------------------------------------------------------------------
// Kernel 4: wl[t,n,o] = relu( sum_m ladj(t,n,m)*support[t,m,o] + biasG[o] )
// ---------------------------------------------------------------------------
__global__ void k_wl(const float* __restrict__ adj, const float* __restrict__ score,
                     const float* __restrict__ biasG)
{
    __shared__ float As[16][64];
    __shared__ float Bs[16][64];
    int t = blockIdx.z;
    int tid = threadIdx.x;
    int m0 = blockIdx.y*64, o0 = blockIdx.x*64;
    int tx = tid & 15, ty = tid >> 4;
    float acc[4][4] = {};
    for (int k0 = 0; k0 < N_; k0 += 16){
        #pragma unroll
        for (int i = 0; i < 4; i++){
            int e = i*256 + tid;
            int r = e >> 4, kk = e & 15;
            int n = m0 + r;
            int m = k0 + kk;
            float v = 0.f;
            if (n < N_){
                float sc = score[(t*N_ + n)*N_ + m];
                if (n < S_ && m < S_)
                    v = (adj[(t*S_ + n)*S_ + m] > 0.f) ? 1.f : -sc;
                else
                    v = sc;
            }
            As[kk][r] = v;
        }
        #pragma unroll
        for (int i = 0; i < 4; i++){
            int e = i*256 + tid;
            int kk = e >> 6, c = e & 63;
            Bs[kk][c] = g_support[(t*N_ + k0 + kk)*GD_ + o0 + c];
        }
        __syncthreads();
        #pragma unroll
        for (int kk = 0; kk < 16; kk++){
            float ra[4], rb[4];
            #pragma unroll
            for (int i = 0; i < 4; i++) ra[i] = As[kk][ty*4 + i];
            #pragma unroll
            for (int jj = 0; jj < 4; jj++) rb[jj] = Bs[kk][tx*4 + jj];
            #pragma unroll
            for (int i = 0; i < 4; i++)
                #pragma unroll
                for (int jj = 0; jj < 4; jj++)
                    acc[i][jj] += ra[i]*rb[jj];
        }
        __syncthreads();
    }
    #pragma unroll
    for (int i = 0; i < 4; i++){
        int n = m0 + ty*4 + i;
        if (n < N_){
            #pragma unroll
            for (int jj = 0; jj < 4; jj++){
                int o = o0 + tx*4 + jj;
                g_wl[(t*N_ + n)*GD_ + o] = fmaxf(acc[i][jj] + biasG[o], 0.f);
            }
        }
    }
}

// ---------------------------------------------------------------------------
// Kernel 5: wl mean over t -> out[0 .. 307200)
// ---------------------------------------------------------------------------
__global__ void k_mean(float* __restrict__ out)
{
    int i = blockIdx.x*blockDim.x + threadIdx.x;
    if (i < N_*GD_){
        float s = g_wl[i] + g_wl[i + N_*GD_] + g_wl[i + 2*N_*GD_] + g_wl[i + 3*N_*GD_];
        out[i] = 0.25f * s;
    }
}

// ---------------------------------------------------------------------------
// Kernel 6: h2a[m,o] = relu( wl[m,:]·W1[o,:] + b[o] )   M=1600, K=768, O=128
// ---------------------------------------------------------------------------
__global__ void k_fc2a(const float* __restrict__ W, const float* __restrict__ bias)
{
    __shared__ float As[16][64];
    __shared__ float Bs[16][64];
    int tid = threadIdx.x;
    int m0 = blockIdx.y*64, o0 = blockIdx.x*64;
    int tx = tid & 15, ty = tid >> 4;
    float acc[4][4] = {};
    for (int k0 = 0; k0 < GD_; k0 += 16){
        #pragma unroll
        for (int i = 0; i < 4; i++){
            int e = i*256 + tid;
            int r = e >> 4, kk = e & 15;
            As[kk][r] = g_wl[(m0 + r)*GD_ + k0 + kk];
        }
        {
            int o  = tid >> 2;
            int kq = (tid & 3)*4;
            float4 w = *(const float4*)&W[(o0 + o)*GD_ + k0 + kq];
            Bs[kq+0][o] = w.x; Bs[kq+1][o] = w.y; Bs[kq+2][o] = w.z; Bs[kq+3][o] = w.w;
        }
        __syncthreads();
        #pragma unroll
        for (int kk = 0; kk < 16; kk++){
            float ra[4], rb[4];
            #pragma unroll
            for (int i = 0; i < 4; i++) ra[i] = As[kk][ty*4 + i];
            #pragma unroll
            for (int jj = 0; jj < 4; jj++) rb[jj] = Bs[kk][tx*4 + jj];
            #pragma unroll
            for (int i = 0; i < 4; i++)
                #pragma unroll
                for (int jj = 0; jj < 4; jj++)
                    acc[i][jj] += ra[i]*rb[jj];
        }
        __syncthreads();
    }
    #pragma unroll
    for (int i = 0; i < 4; i++)
        #pragma unroll
        for (int jj = 0; jj < 4; jj++){
            int o = o0 + tx*4 + jj;
            g_h2a[(m0 + ty*4 + i)*H1_ + o] = fmaxf(acc[i][jj] + bias[o], 0.f);
        }
}

// ---------------------------------------------------------------------------
// Kernel 7: h2b[m,o] = relu( h2a[m,:]·W2[o,:] + b[o] )   M=1600, K=128, O=128
// ---------------------------------------------------------------------------
__global__ void k_fc2b(const float* __restrict__ W, const float* __restrict__ bias)
{
    __shared__ float As[16][64];
    __shared__ float Bs[16][64];
    int tid = threadIdx.x;
    int m0 = blockIdx.y*64, o0 = blockIdx.x*64;
    int tx = tid & 15, ty = tid >> 4;
    float acc[4][4] = {};
    for (int k0 = 0; k0 < H1_; k0 += 16){
        #pragma unroll
        for (int i = 0; i < 4; i++){
            int e = i*256 + tid;
            int r = e >> 4, kk = e & 15;
            As[kk][r] = g_h2a[(m0 + r)*H1_ + k0 + kk];
        }
        {
            int o  = tid >> 2;
            int kq = (tid & 3)*4;
            float4 w = *(const float4*)&W[(o0 + o)*H1_ + k0 + kq];
            Bs[kq+0][o] = w.x; Bs[kq+1][o] = w.y; Bs[kq+2][o] = w.z; Bs[kq+3][o] = w.w;
        }
        __syncthreads();
        #pragma unroll
        for (int kk = 0; kk < 16; kk++){
            float ra[4], rb[4];
            #pragma unroll
            for (int i = 0; i < 4; i++) ra[i] = As[kk][ty*4 + i];
            #pragma unroll
            for (int jj = 0; jj < 4; jj++) rb[jj] = Bs[kk][tx*4 + jj];
            #pragma unroll
            for (int i = 0; i < 4; i++)
                #pragma unroll
                for (int jj = 0; jj < 4; jj++)
                    acc[i][jj] += ra[i]*rb[jj];
        }
        __syncthreads();
    }
    #pragma unroll
    for (int i = 0; i < 4; i++)
        #pragma unroll
        for (int jj = 0; jj < 4; jj++){
            int o = o0 + tx*4 + jj;
            g_h2b[(m0 + ty*4 + i)*H1_ + o] = fmaxf(acc[i][jj] + bias[o], 0.f);
        }
}

// ---------------------------------------------------------------------------
// Kernel 8: query[t,c,n] = sigmoid( h2b[t,n,:]·w3[c,:] + b3[c] )
// ---------------------------------------------------------------------------
__global__ void k_query(const float* __restrict__ w3, const float* __restrict__ b3,
                        float* __restrict__ out)
{
    int idx = blockIdx.x*blockDim.x + threadIdx.x;
    if (idx >= TNROWS*5) return;
    int row = idx / 5, c = idx % 5;
    const float* h = g_h2b + row*H1_;
    const float* w = w3 + c*H1_;
    float s = 0.f;
    #pragma unroll 8
    for (int k = 0; k < H1_; k++) s += h[k]*w[k];
    int t = row / N_, n = row % N_;
    out[OUT_QS + t*5*N_ + c*N_ + n] = sigmoidf_(s + b3[c]);
}

// ---------------------------------------------------------------------------
extern "C" void kernel_launch(void* const* d_in, const int* in_sizes, int n_in,
                              void* d_out, int out_size)
{
    const float* nf       = (const float*)d_in[0];
    const float* adj      = (const float*)d_in[1];
    const float* fc1_w1   = (const float*)d_in[2];
    const float* fc1_b1   = (const float*)d_in[3];
    const float* fc1_w2   = (const float*)d_in[4];
    const float* fc1_b2   = (const float*)d_in[5];
    const float* fc1_w3   = (const float*)d_in[6];
    const float* fc1_b3   = (const float*)d_in[7];
    const float* weight_G = (const float*)d_in[8];
    const float* bias_G   = (const float*)d_in[9];
    const float* fc2_w1   = (const float*)d_in[10];
    const float* fc2_b1   = (const float*)d_in[11];
    const float* fc2_w2   = (const float*)d_in[12];
    const float* fc2_b2   = (const float*)d_in[13];
    const float* fc2_w3   = (const float*)d_in[14];
    const float* fc2_b3   = (const float*)d_in[15];

    float* out       = (float*)d_out;
    float* score_out = out + OUT_SCORE;

    size_t smem_pair = (size_t)(2*128*ROWH)*sizeof(__half)
                     + (size_t)(H0_ + H1_ + H1_ + H1_)*sizeof(float);
    cudaFuncSetAttribute(k_pair, cudaFuncAttributeMaxDynamicSharedMemorySize, (int)smem_pair);

    k_pre<<<dim3(8, 25), 256>>>(nf, fc1_w1);
    k_pair<<<TNROWS, 256, smem_pair>>>(fc1_b1, fc1_w2, fc1_b2, fc1_w3, fc1_b3, score_out);
    k_support<<<dim3(GD_/64, TNROWS/64), 256>>>(nf, weight_G);
    k_wl<<<dim3(GD_/64, (N_ + 63)/64, T_), 256>>>(adj, score_out, bias_G);
    k_mean<<<(N_*GD_ + 255)/256, 256>>>(out);
    k_fc2a<<<dim3(H1_/64, TNROWS/64), 256>>>(fc2_w1, fc2_b1);
    k_fc2b<<<dim3(H1_/64, TNROWS/64), 256>>>(fc2_w2, fc2_b2);
    k_query<<<(TNROWS*5 + 127)/128, 128>>>(fc2_w3, fc2_b3, out);
}

// round 7
// speedup vs baseline: 7.0927x; 1.1479x over previous
#include <cuda_runtime.h>
#include <cuda_fp16.h>
#include <math.h>

#define T_  4
#define N_  400
#define S_  395
#define D_  128
#define H0_ 256
#define H1_ 128
#define GD_ 768
#define TNROWS (T_*N_)           // 1600

// output layout: [wl_mean (400*768)] [learned_score (4*400*400)] [query^T (4*5*400)]
#define OUT_SCORE (N_*GD_)               // 307200
#define OUT_QS    (OUT_SCORE + T_*N_*N_) // 947200

#define ROWH 264                 // padded half-row stride for k_pair ldmatrix tiles

__device__ float  g_A[TNROWS*H0_];
__device__ float  g_B[TNROWS*H0_];
__device__ __half g_supH[TNROWS*GD_];
__device__ __half g_supL[TNROWS*GD_];
__device__ float  g_wl[TNROWS*GD_];
__device__ float  g_h2a[TNROWS*H1_];
__device__ float  g_h2b[TNROWS*H1_];

__device__ __forceinline__ float sigmoidf_(float x){ return 1.0f/(1.0f + __expf(-x)); }

__device__ __forceinline__ void ldsm_x4(unsigned* r, unsigned addr){
    asm volatile("ldmatrix.sync.aligned.m8n8.x4.shared.b16 {%0,%1,%2,%3}, [%4];"
        : "=r"(r[0]), "=r"(r[1]), "=r"(r[2]), "=r"(r[3]) : "r"(addr));
}
__device__ __forceinline__ void ldsm_x4_t(unsigned* r, unsigned addr){
    asm volatile("ldmatrix.sync.aligned.m8n8.x4.trans.shared.b16 {%0,%1,%2,%3}, [%4];"
        : "=r"(r[0]), "=r"(r[1]), "=r"(r[2]), "=r"(r[3]) : "r"(addr));
}
__device__ __forceinline__ void mma16816(float* d, const unsigned* a, const unsigned* b){
    asm volatile("mma.sync.aligned.m16n8k16.row.col.f32.f16.f16.f32 "
        "{%0,%1,%2,%3},{%4,%5,%6,%7},{%8,%9},{%0,%1,%2,%3};"
        : "+f"(d[0]), "+f"(d[1]), "+f"(d[2]), "+f"(d[3])
        : "r"(a[0]), "r"(a[1]), "r"(a[2]), "r"(a[3]), "r"(b[0]), "r"(b[1]));
}

// One BK=64 stage of a 128x128 block tile; 8 warps as 2(M)x4(N), warp tile m64n32.
// A smem layout [m][k] (pad PA halves). B smem layout [k][j] (pad PB) -> trans ldsm.
__device__ __forceinline__ void mma64_trans(float d[4][4][4], unsigned Asu, unsigned Bsu,
                                            int lane, int warp_m, int warp_n, int PA, int PB)
{
    int ar = lane & 15, ac = (lane >> 4) * 8;
    int bk = ((lane >> 3) & 1) * 8 + (lane & 7);
    int bj = ((lane >> 4) & 1) * 8;
    #pragma unroll
    for (int ks = 0; ks < 4; ks++){
        unsigned a[4][4], b[2][4];
        #pragma unroll
        for (int mt = 0; mt < 4; mt++)
            ldsm_x4(a[mt], Asu + (unsigned)(((warp_m*64 + mt*16 + ar)*PA + ks*16 + ac)*2));
        #pragma unroll
        for (int nb = 0; nb < 2; nb++)
            ldsm_x4_t(b[nb], Bsu + (unsigned)(((ks*16 + bk)*PB + warp_n*32 + nb*16 + bj)*2));
        #pragma unroll
        for (int mt = 0; mt < 4; mt++)
            #pragma unroll
            for (int nb = 0; nb < 2; nb++){
                mma16816(d[mt][nb*2+0], a[mt], &b[nb][0]);
                mma16816(d[mt][nb*2+1], a[mt], &b[nb][2]);
            }
    }
}
#define ZERO_D(d) { _Pragma("unroll") for (int i=0;i<4;i++) _Pragma("unroll") for (int j=0;j<4;j++) _Pragma("unroll") for (int v=0;v<4;v++) (d)[i][j][v]=0.f; }

__device__ __forceinline__ void split2(float x, __half& h, __half& l){
    h = __float2half_rn(x);
    l = __float2half_rn(x - __half2float(h));
}

// ---------------------------------------------------------------------------
// Kernel 1 (GEMM form): out[m, h'] = nf[m,:]·W1c[h',:]  for h' in [0,512)
// ---------------------------------------------------------------------------
__global__ void k_pre(const float* __restrict__ nf, const float* __restrict__ w1)
{
    __shared__ float As[16][64];
    __shared__ float Bs[16][64];
    int tid = threadIdx.x;
    int m0 = blockIdx.y*64, h0 = blockIdx.x*64;
    int tx = tid & 15, ty = tid >> 4;
    float acc[4][4] = {};
    for (int k0 = 0; k0 < D_; k0 += 16){
        #pragma unroll
        for (int i = 0; i < 4; i++){
            int e = i*256 + tid;
            int r = e >> 4, kk = e & 15;
            int m = m0 + r;
            As[kk][r] = nf[m*D_ + k0 + kk];
        }
        {
            int o  = tid >> 2;
            int kq = (tid & 3)*4;
            int hp = h0 + o;
            const float* src = w1 + (hp & 255)*(2*D_) + (hp >> 8)*D_ + k0 + kq;
            float4 w = *(const float4*)src;
            Bs[kq+0][o] = w.x; Bs[kq+1][o] = w.y; Bs[kq+2][o] = w.z; Bs[kq+3][o] = w.w;
        }
        __syncthreads();
        #pragma unroll
        for (int kk = 0; kk < 16; kk++){
            float ra[4], rb[4];
            #pragma unroll
            for (int i = 0; i < 4; i++) ra[i] = As[kk][ty*4 + i];
            #pragma unroll
            for (int jj = 0; jj < 4; jj++) rb[jj] = Bs[kk][tx*4 + jj];
            #pragma unroll
            for (int i = 0; i < 4; i++)
                #pragma unroll
                for (int jj = 0; jj < 4; jj++)
                    acc[i][jj] += ra[i]*rb[jj];
        }
        __syncthreads();
    }
    #pragma unroll
    for (int i = 0; i < 4; i++)
        #pragma unroll
        for (int jj = 0; jj < 4; jj++){
            int hp = h0 + tx*4 + jj;
            float* dst = (hp < H0_) ? g_A : g_B;
            dst[(m0 + ty*4 + i)*H0_ + (hp & 255)] = acc[i][jj];
        }
}

// ---------------------------------------------------------------------------
// Kernel 2: pairwise MLP via fp16 tensor-core GEMM (unchanged; passes @9.4e-5)
// ---------------------------------------------------------------------------
__global__ void __launch_bounds__(256, 1)
k_pair(const float* __restrict__ b1v, const float* __restrict__ w2,
       const float* __restrict__ b2v, const float* __restrict__ w3,
       const float* __restrict__ b3v, float* __restrict__ score_out)
{
    extern __shared__ char smraw[];
    __half* h1s  = (__half*)smraw;                    // 128 * 264
    __half* W2s  = h1s + 128*ROWH;                    // 128 * 264
    float*  Arb1 = (float*)(W2s + 128*ROWH);          // 256
    float*  sred = Arb1 + H0_;                        // 128
    float*  b2s  = sred + H1_;                        // 128
    float*  w3s  = b2s + H1_;                         // 128

    int blk  = blockIdx.x;                            // t*N_ + a
    int t    = blk / N_;
    int tid  = threadIdx.x;
    int lane = tid & 31;
    int wid  = tid >> 5;
    int warp_n = wid & 3;
    int warp_m = wid >> 2;

    for (int idx = tid; idx < 128*64; idx += 256){
        int row = idx >> 6, c4 = idx & 63;
        float4 w = *(const float4*)&w2[row*H0_ + c4*4];
        *(__half2*)&W2s[row*ROWH + c4*4]     = __floats2half2_rn(w.x, w.y);
        *(__half2*)&W2s[row*ROWH + c4*4 + 2] = __floats2half2_rn(w.z, w.w);
    }
    Arb1[tid] = g_A[blk*H0_ + tid] + b1v[tid];
    if (tid < H1_){ b2s[tid] = b2v[tid]; w3s[tid] = w3[tid]; }
    float b3 = b3v[0];

    unsigned h1u = (unsigned)__cvta_generic_to_shared(h1s);
    unsigned w2u = (unsigned)__cvta_generic_to_shared(W2s);

    int a_trow  = lane & 15;
    int a_tcol8 = (lane >> 4) * 8;
    int b_g     = lane >> 3;
    int b_i     = lane & 7;
    int b_joff  = ((b_g >= 2) ? 8 : 0) + b_i;
    int b_koff  = (b_g & 1) * 8;

    for (int b0 = 0; b0 < N_; b0 += 128){
        __syncthreads();
        for (int idx = tid; idx < 128*64; idx += 256){
            int row = idx >> 6, c4 = idx & 63;
            int bg = b0 + row;
            float4 v;
            if (bg < N_) v = *(const float4*)&g_B[((t*N_ + bg)*H0_) + c4*4];
            else         v = make_float4(0.f,0.f,0.f,0.f);
            float h0f = fmaxf(v.x + Arb1[c4*4+0], 0.f);
            float h1f = fmaxf(v.y + Arb1[c4*4+1], 0.f);
            float h2f = fmaxf(v.z + Arb1[c4*4+2], 0.f);
            float h3f = fmaxf(v.w + Arb1[c4*4+3], 0.f);
            *(__half2*)&h1s[row*ROWH + c4*4]     = __floats2half2_rn(h0f, h1f);
            *(__half2*)&h1s[row*ROWH + c4*4 + 2] = __floats2half2_rn(h2f, h3f);
        }
        if (tid < H1_) sred[tid] = 0.f;
        __syncthreads();

        float d[4][4][4];
        ZERO_D(d);

        unsigned aA[4], bA[2];
        #pragma unroll
        for (int mt = 0; mt < 4; mt++)
            aA[mt] = h1u + ((warp_m*64 + mt*16 + a_trow)*ROWH + a_tcol8)*2;
        #pragma unroll
        for (int nb = 0; nb < 2; nb++)
            bA[nb] = w2u + ((warp_n*32 + nb*16 + b_joff)*ROWH + b_koff)*2;

        for (int ks = 0; ks < 16; ks++){
            unsigned a[4][4], b[2][4];
            #pragma unroll
            for (int mt = 0; mt < 4; mt++) ldsm_x4(a[mt], aA[mt] + ks*32);
            #pragma unroll
            for (int nb = 0; nb < 2; nb++) ldsm_x4(b[nb], bA[nb] + ks*32);
            #pragma unroll
            for (int mt = 0; mt < 4; mt++){
                #pragma unroll
                for (int nb = 0; nb < 2; nb++){
                    mma16816(d[mt][nb*2+0], a[mt], &b[nb][0]);
                    mma16816(d[mt][nb*2+1], a[mt], &b[nb][2]);
                }
            }
        }

        #pragma unroll
        for (int mt = 0; mt < 4; mt++){
            #pragma unroll
            for (int h = 0; h < 2; h++){
                float part = 0.f;
                #pragma unroll
                for (int n8 = 0; n8 < 4; n8++){
                    #pragma unroll
                    for (int c = 0; c < 2; c++){
                        int j = warp_n*32 + n8*8 + (lane & 3)*2 + c;
                        float val = d[mt][n8][h*2 + c] + b2s[j];
                        part += fmaxf(val, 0.f) * w3s[j];
                    }
                }
                part += __shfl_xor_sync(0xffffffff, part, 1);
                part += __shfl_xor_sync(0xffffffff, part, 2);
                if ((lane & 3) == 0){
                    int row = warp_m*64 + mt*16 + (lane >> 2) + h*8;
                    atomicAdd(&sred[row], part);
                }
            }
        }
        __syncthreads();

        if (tid < H1_){
            int bg = b0 + tid;
            if (bg < N_)
                score_out[blk*N_ + bg] = sigmoidf_(sred[tid] + b3);
        }
    }
}

// ---------------------------------------------------------------------------
// Kernel 3: support = gcn_in·Wg via SPLIT fp16 MMA (3 passes ≈ fp32 accuracy)
// Stores support as hi/lo fp16 pair.
// ---------------------------------------------------------------------------
__global__ void __launch_bounds__(256)
k_support(const float* __restrict__ nf, const float* __restrict__ Wg)
{
    extern __shared__ char smraw[];
    __half* Ah = (__half*)smraw;        // [128][72]
    __half* Al = Ah + 128*72;           // [128][72]
    __half* Bh = Al + 128*72;           // [64][136]
    __half* Bl = Bh + 64*136;           // [64][136]
    int tid = threadIdx.x, lane = tid & 31, wid = tid >> 5;
    int warp_n = wid & 3, warp_m = wid >> 2;
    int o0 = blockIdx.x*128, m0 = blockIdx.y*128;
    unsigned Ahu = (unsigned)__cvta_generic_to_shared(Ah);
    unsigned Alu = (unsigned)__cvta_generic_to_shared(Al);
    unsigned Bhu = (unsigned)__cvta_generic_to_shared(Bh);
    unsigned Blu = (unsigned)__cvta_generic_to_shared(Bl);
    float d[4][4][4];
    ZERO_D(d);

    for (int k0 = 0; k0 < GD_; k0 += 64){
        for (int idx = tid; idx < 128*16; idx += 256){
            int row = idx >> 4, c4 = idx & 15;
            int m = m0 + row, f = k0 + c4*4;
            float4 v = make_float4(0.f,0.f,0.f,0.f);
            if (m < TNROWS){
                int tt = m / N_, n = m % N_;
                int node = (f < D_) ? n : (S_ + (f >> 7) - 1);
                v = *(const float4*)&nf[(tt*N_ + node)*D_ + (f & 127)];
            }
            __half h0,l0,h1,l1,h2,l2,h3,l3;
            split2(v.x,h0,l0); split2(v.y,h1,l1); split2(v.z,h2,l2); split2(v.w,h3,l3);
            *(__half2*)&Ah[row*72 + c4*4]     = __halves2half2(h0,h1);
            *(__half2*)&Ah[row*72 + c4*4 + 2] = __halves2half2(h2,h3);
            *(__half2*)&Al[row*72 + c4*4]     = __halves2half2(l0,l1);
            *(__half2*)&Al[row*72 + c4*4 + 2] = __halves2half2(l2,l3);
        }
        for (int idx = tid; idx < 64*32; idx += 256){
            int row = idx >> 5, c4 = idx & 31;
            float4 v = *(const float4*)&Wg[(k0 + row)*GD_ + o0 + c4*4];
            __half h0,l0,h1,l1,h2,l2,h3,l3;
            split2(v.x,h0,l0); split2(v.y,h1,l1); split2(v.z,h2,l2); split2(v.w,h3,l3);
            *(__half2*)&Bh[row*136 + c4*4]     = __halves2half2(h0,h1);
            *(__half2*)&Bh[row*136 + c4*4 + 2] = __halves2half2(h2,h3);
            *(__half2*)&Bl[row*136 + c4*4]     = __halves2half2(l0,l1);
            *(__half2*)&Bl[row*136 + c4*4 + 2] = __halves2half2(l2,l3);
        }
        __syncthreads();
        mma64_trans(d, Ahu, Bhu, lane, warp_m, warp_n, 72, 136);
        mma64_trans(d, Ahu, Blu, lane, warp_m, warp_n, 72, 136);
        mma64_trans(d, Alu, Bhu, lane, warp_m, warp_n, 72, 136);
        __syncthreads();
    }
    #pragma unroll
    for (int mt = 0; mt < 4; mt++)
        #pragma unroll
        for (int n8 = 0; n8 < 4; n8++)
            #pragma unroll
            for (int v = 0; v < 4; v++){
                int row = m0 + warp_m*64 + mt*16 + (lane >> 2) + (v >> 1)*8;
                int col = o0 + warp_n*32 + n8*8 + (lane & 3)*2 + (v & 1);
                if (row < TNROWS){
                    __half h, l;
                    split2(d[mt][n8][v], h, l);
                    g_supH[row*GD_ + col] = h;
                    g_supL[row*GD_ + col] = l;
                }
            }
}

// ---------------------------------------------------------------------------
// Kernel 4: wl = relu( ladj·support + biasG ), B = hi+lo (2 passes)
// ---------------------------------------------------------------------------
__global__ void __launch_bounds__(256)
k_wl(const float* __restrict__ adj, const float* __restrict__ score,
     const float* __restrict__ biasG)
{
    extern __shared__ char smraw[];
    __half* As = (__half*)smraw;        // [128][72]
    __half* Bh = As + 128*72;           // [64][136]
    __half* Bl = Bh + 64*136;           // [64][136]
    int tid = threadIdx.x, lane = tid & 31, wid = tid >> 5;
    int warp_n = wid & 3, warp_m = wid >> 2;
    int o0 = blockIdx.x*128, m0 = blockIdx.y*128, t = blockIdx.z;
    unsigned Asu = (unsigned)__cvta_generic_to_shared(As);
    unsigned Bhu = (unsigned)__cvta_generic_to_shared(Bh);
    unsigned Blu = (unsigned)__cvta_generic_to_shared(Bl);
    float d[4][4][4];
    ZERO_D(d);

    for (int k0 = 0; k0 < N_; k0 += 64){
        for (int idx = tid; idx < 128*16; idx += 256){
            int row = idx >> 4, c4 = idx & 15;
            int n = m0 + row, k = k0 + c4*4;
            float v0=0.f, v1=0.f, v2=0.f, v3=0.f;
            if (n < N_ && k < N_){
                float4 sc = *(const float4*)&score[(t*N_ + n)*N_ + k];
                v0 = sc.x; v1 = sc.y; v2 = sc.z; v3 = sc.w;
                if (n < S_){
                    if (k+0 < S_) v0 = (adj[(t*S_ + n)*S_ + k+0] > 0.f) ? 1.f : -v0;
                    if (k+1 < S_) v1 = (adj[(t*S_ + n)*S_ + k+1] > 0.f) ? 1.f : -v1;
                    if (k+2 < S_) v2 = (adj[(t*S_ + n)*S_ + k+2] > 0.f) ? 1.f : -v2;
                    if (k+3 < S_) v3 = (adj[(t*S_ + n)*S_ + k+3] > 0.f) ? 1.f : -v3;
                }
            }
            *(__half2*)&As[row*72 + c4*4]     = __floats2half2_rn(v0, v1);
            *(__half2*)&As[row*72 + c4*4 + 2] = __floats2half2_rn(v2, v3);
        }
        for (int idx = tid; idx < 64*16; idx += 256){
            int row = idx >> 4, c8 = idx & 15;
            int k = k0 + row;
            uint4 vh = make_uint4(0u,0u,0u,0u);
            uint4 vl = make_uint4(0u,0u,0u,0u);
            if (k < N_){
                vh = *(const uint4*)&g_supH[(t*N_ + k)*GD_ + o0 + c8*8];
                vl = *(const uint4*)&g_supL[(t*N_ + k)*GD_ + o0 + c8*8];
            }
            *(uint4*)&Bh[row*136 + c8*8] = vh;
            *(uint4*)&Bl[row*136 + c8*8] = vl;
        }
        __syncthreads();
        mma64_trans(d, Asu, Bhu, lane, warp_m, warp_n, 72, 136);
        mma64_trans(d, Asu, Blu, lane, warp_m, warp_n, 72, 136);
        __syncthreads();
    }
    #pragma unroll
    for (int mt = 0; mt < 4; mt++)
        #pragma unroll
        for (int n8 = 0; n8 < 4; n8++)
            #pragma unroll
            for (int v = 0; v < 4; v++){
                int n = m0 + warp_m*64 + mt*16 + (lane >> 2) + (v >> 1)*8;
                int o = o0 + warp_n*32 + n8*8 + (lane & 3)*2 + (v & 1);
                if (n < N_)
                    g_wl[(t*N_ + n)*GD_ + o] = fmaxf(d[mt][n8][v] + biasG[o], 0.f);
            }
}

// ---------------------------------------------------------------------------
// Kernel 5: wl mean over t -> out[0 .. 307200)
// ---------------------------------------------------------------------------
__global__ void k_mean(float* __restrict__ out)
{
    int i = blockIdx.x*blockDim.x + threadIdx.x;
    if (i < N_*GD_){
        float s = g_wl[i] + g_wl[i + N_*GD_] + g_wl[i + 2*N_*GD_] + g_wl[i + 3*N_*GD_];
        out[i] = 0.25f * s;
    }
}

// ---------------------------------------------------------------------------
// Kernel 6: h2a[m,o] = relu( wl[m,:]·W1[o,:] + b[o] )  fp32  M=1600,K=768,O=128
// ---------------------------------------------------------------------------
__global__ void k_fc2a(const float* __restrict__ W, const float* __restrict__ bias)
{
    __shared__ float As[16][64];
    __shared__ float Bs[16][64];
    int tid = threadIdx.x;
    int m0 = blockIdx.y*64, o0 = blockIdx.x*64;
    int tx = tid & 15, ty = tid >> 4;
    float acc[4][4] = {};
    for (int k0 = 0; k0 < GD_; k0 += 16){
        #pragma unroll
        for (int i = 0; i < 4; i++){
            int e = i*256 + tid;
            int r = e >> 4, kk = e & 15;
            As[kk][r] = g_wl[(m0 + r)*GD_ + k0 + kk];
        }
        {
            int o  = tid >> 2;
            int kq = (tid & 3)*4;
            float4 w = *(const float4*)&W[(o0 + o)*GD_ + k0 + kq];
            Bs[kq+0][o] = w.x; Bs[kq+1][o] = w.y; Bs[kq+2][o] = w.z; Bs[kq+3][o] = w.w;
        }
        __syncthreads();
        #pragma unroll
        for (int kk = 0; kk < 16; kk++){
            float ra[4], rb[4];
            #pragma unroll
            for (int i = 0; i < 4; i++) ra[i] = As[kk][ty*4 + i];
            #pragma unroll
            for (int jj = 0; jj < 4; jj++) rb[jj] = Bs[kk][tx*4 + jj];
            #pragma unroll
            for (int i = 0; i < 4; i++)
                #pragma unroll
                for (int jj = 0; jj < 4; jj++)
                    acc[i][jj] += ra[i]*rb[jj];
        }
        __syncthreads();
    }
    #pragma unroll
    for (int i = 0; i < 4; i++)
        #pragma unroll
        for (int jj = 0; jj < 4; jj++){
            int o = o0 + tx*4 + jj;
            g_h2a[(m0 + ty*4 + i)*H1_ + o] = fmaxf(acc[i][jj] + bias[o], 0.f);
        }
}

// ---------------------------------------------------------------------------
// Kernel 7: h2b[m,o] = relu( h2a[m,:]·W2[o,:] + b[o] )  fp32  M=1600,K=128,O=128
// ---------------------------------------------------------------------------
__global__ void k_fc2b(const float* __restrict__ W, const float* __restrict__ bias)
{
    __shared__ float As[16][64];
    __shared__ float Bs[16][64];
    int tid = threadIdx.x;
    int m0 = blockIdx.y*64, o0 = blockIdx.x*64;
    int tx = tid & 15, ty = tid >> 4;
    float acc[4][4] = {};
    for (int k0 = 0; k0 < H1_; k0 += 16){
        #pragma unroll
        for (int i = 0; i < 4; i++){
            int e = i*256 + tid;
            int r = e >> 4, kk = e & 15;
            As[kk][r] = g_h2a[(m0 + r)*H1_ + k0 + kk];
        }
        {
            int o  = tid >> 2;
            int kq = (tid & 3)*4;
            float4 w = *(const float4*)&W[(o0 + o)*H1_ + k0 + kq];
            Bs[kq+0][o] = w.x; Bs[kq+1][o] = w.y; Bs[kq+2][o] = w.z; Bs[kq+3][o] = w.w;
        }
        __syncthreads();
        #pragma unroll
        for (int kk = 0; kk < 16; kk++){
            float ra[4], rb[4];
            #pragma unroll
            for (int i = 0; i < 4; i++) ra[i] = As[kk][ty*4 + i];
            #pragma unroll
            for (int jj = 0; jj < 4; jj++) rb[jj] = Bs[kk][tx*4 + jj];
            #pragma unroll
            for (int i = 0; i < 4; i++)
                #pragma unroll
                for (int jj = 0; jj < 4; jj++)
                    acc[i][jj] += ra[i]*rb[jj];
        }
        __syncthreads();
    }
    #pragma unroll
    for (int i = 0; i < 4; i++)
        #pragma unroll
        for (int jj = 0; jj < 4; jj++){
            int o = o0 + tx*4 + jj;
            g_h2b[(m0 + ty*4 + i)*H1_ + o] = fmaxf(acc[i][jj] + bias[o], 0.f);
        }
}

// ---------------------------------------------------------------------------
// Kernel 8: query[t,c,n] = sigmoid( h2b[t,n,:]·w3[c,:] + b3[c] )
// ---------------------------------------------------------------------------
__global__ void k_query(const float* __restrict__ w3, const float* __restrict__ b3,
                        float* __restrict__ out)
{
    int idx = blockIdx.x*blockDim.x + threadIdx.x;
    if (idx >= TNROWS*5) return;
    int row = idx / 5, c = idx % 5;
    const float* h = g_h2b + row*H1_;
    const float* w = w3 + c*H1_;
    float s = 0.f;
    #pragma unroll 8
    for (int k = 0; k < H1_; k++) s += h[k]*w[k];
    int t = row / N_, n = row % N_;
    out[OUT_QS + t*5*N_ + c*N_ + n] = sigmoidf_(s + b3[c]);
}

// ---------------------------------------------------------------------------
extern "C" void kernel_launch(void* const* d_in, const int* in_sizes, int n_in,
                              void* d_out, int out_size)
{
    const float* nf       = (const float*)d_in[0];
    const float* adj      = (const float*)d_in[1];
    const float* fc1_w1   = (const float*)d_in[2];
    const float* fc1_b1   = (const float*)d_in[3];
    const float* fc1_w2   = (const float*)d_in[4];
    const float* fc1_b2   = (const float*)d_in[5];
    const float* fc1_w3   = (const float*)d_in[6];
    const float* fc1_b3   = (const float*)d_in[7];
    const float* weight_G = (const float*)d_in[8];
    const float* bias_G   = (const float*)d_in[9];
    const float* fc2_w1   = (const float*)d_in[10];
    const float* fc2_b1   = (const float*)d_in[11];
    const float* fc2_w2   = (const float*)d_in[12];
    const float* fc2_b2   = (const float*)d_in[13];
    const float* fc2_w3   = (const float*)d_in[14];
    const float* fc2_b3   = (const float*)d_in[15];

    float* out       = (float*)d_out;
    float* score_out = out + OUT_SCORE;

    size_t smem_pair = (size_t)(2*128*ROWH)*sizeof(__half)
                     + (size_t)(H0_ + H1_ + H1_ + H1_)*sizeof(float);
    cudaFuncSetAttribute(k_pair, cudaFuncAttributeMaxDynamicSharedMemorySize, (int)smem_pair);
    size_t smem_sup = (size_t)(2*128*72 + 2*64*136)*sizeof(__half);   // 71680
    cudaFuncSetAttribute(k_support, cudaFuncAttributeMaxDynamicSharedMemorySize, (int)smem_sup);
    size_t smem_wl  = (size_t)(128*72 + 2*64*136)*sizeof(__half);     // 53248
    cudaFuncSetAttribute(k_wl, cudaFuncAttributeMaxDynamicSharedMemorySize, (int)smem_wl);

    k_pre<<<dim3(8, 25), 256>>>(nf, fc1_w1);
    k_pair<<<TNROWS, 256, smem_pair>>>(fc1_b1, fc1_w2, fc1_b2, fc1_w3, fc1_b3, score_out);
    k_support<<<dim3(GD_/128, (TNROWS + 127)/128), 256, smem_sup>>>(nf, weight_G);
    k_wl<<<dim3(GD_/128, (N_ + 127)/128, T_), 256, smem_wl>>>(adj, score_out, bias_G);
    k_mean<<<(N_*GD_ + 255)/256, 256>>>(out);
    k_fc2a<<<dim3(H1_/64, TNROWS/64), 256>>>(fc2_w1, fc2_b1);
    k_fc2b<<<dim3(H1_/64, TNROWS/64), 256>>>(fc2_w2, fc2_b2);
    k_query<<<(TNROWS*5 + 127)/128, 128>>>(fc2_w3, fc2_b3, out);
}

// round 8
// speedup vs baseline: 10.3317x; 1.4567x over previous
#include <cuda_runtime.h>
#include <cuda_fp16.h>
#include <math.h>

#define T_  4
#define N_  400
#define S_  395
#define D_  128
#define H0_ 256
#define H1_ 128
#define GD_ 768
#define TNROWS (T_*N_)           // 1600

// output layout: [wl_mean (400*768)] [learned_score (4*400*400)] [query^T (4*5*400)]
#define OUT_SCORE (N_*GD_)               // 307200
#define OUT_QS    (OUT_SCORE + T_*N_*N_) // 947200

#define ROWH 264                 // padded half-row stride for k_pair ldmatrix tiles

__device__ __half g_ABh[TNROWS*H0_];     // fp16(A + b1)
__device__ __half g_Bh [TNROWS*H0_];     // fp16(B)
__device__ __half g_W2h[H1_*H0_];        // fp16(fc1_w2)
__device__ __half g_ladjH[T_*N_*N_];     // fp16(learned_adj)
__device__ __half g_supH[TNROWS*GD_];
__device__ __half g_supL[TNROWS*GD_];
__device__ float  g_wl[TNROWS*GD_];
__device__ float  g_h2a[TNROWS*H1_];
__device__ float  g_h2b[TNROWS*H1_];

__device__ __forceinline__ float sigmoidf_(float x){ return 1.0f/(1.0f + __expf(-x)); }

__device__ __forceinline__ void ldsm_x4(unsigned* r, unsigned addr){
    asm volatile("ldmatrix.sync.aligned.m8n8.x4.shared.b16 {%0,%1,%2,%3}, [%4];"
        : "=r"(r[0]), "=r"(r[1]), "=r"(r[2]), "=r"(r[3]) : "r"(addr));
}
__device__ __forceinline__ void ldsm_x4_t(unsigned* r, unsigned addr){
    asm volatile("ldmatrix.sync.aligned.m8n8.x4.trans.shared.b16 {%0,%1,%2,%3}, [%4];"
        : "=r"(r[0]), "=r"(r[1]), "=r"(r[2]), "=r"(r[3]) : "r"(addr));
}
__device__ __forceinline__ void mma16816(float* d, const unsigned* a, const unsigned* b){
    asm volatile("mma.sync.aligned.m16n8k16.row.col.f32.f16.f16.f32 "
        "{%0,%1,%2,%3},{%4,%5,%6,%7},{%8,%9},{%0,%1,%2,%3};"
        : "+f"(d[0]), "+f"(d[1]), "+f"(d[2]), "+f"(d[3])
        : "r"(a[0]), "r"(a[1]), "r"(a[2]), "r"(a[3]), "r"(b[0]), "r"(b[1]));
}

__device__ __forceinline__ void split2(float x, __half& h, __half& l){
    h = __float2half_rn(x);
    l = __float2half_rn(x - __half2float(h));
}

// -------- 64x64-tile helpers: 8 warps, warp tile m16 x n32 --------
// warp_m = wid>>1 (0..3), warp_n = wid&1. d[4][4] accum (4 n8-groups x 4 vals).
// A smem [m][k] pad PA. B trans: smem [k][j] pad PB. One 64-K step.
__device__ __forceinline__ void mma_m16n32_t(float d[4][4], unsigned Asu, unsigned Bsu,
                                             int lane, int warp_m, int warp_n, int PA, int PB)
{
    int ar = lane & 15, ac = (lane >> 4) * 8;
    int bk = ((lane >> 3) & 1) * 8 + (lane & 7);
    int bj = ((lane >> 4) & 1) * 8;
    #pragma unroll
    for (int ks = 0; ks < 4; ks++){
        unsigned a[4], b[2][4];
        ldsm_x4(a, Asu + (unsigned)(((warp_m*16 + ar)*PA + ks*16 + ac)*2));
        #pragma unroll
        for (int nb = 0; nb < 2; nb++)
            ldsm_x4_t(b[nb], Bsu + (unsigned)(((ks*16 + bk)*PB + warp_n*32 + nb*16 + bj)*2));
        #pragma unroll
        for (int nb = 0; nb < 2; nb++){
            mma16816(d[nb*2+0], a, &b[nb][0]);
            mma16816(d[nb*2+1], a, &b[nb][2]);
        }
    }
}
// B normal: smem [j][k] pad PB.
__device__ __forceinline__ void mma_m16n32_n(float d[4][4], unsigned Asu, unsigned Bsu,
                                             int lane, int warp_m, int warp_n, int PA, int PB)
{
    int ar = lane & 15, ac = (lane >> 4) * 8;
    int bg = lane >> 3;
    int bj = ((bg >= 2) ? 8 : 0) + (lane & 7);
    int bk2 = (bg & 1) * 8;
    #pragma unroll
    for (int ks = 0; ks < 4; ks++){
        unsigned a[4], b[2][4];
        ldsm_x4(a, Asu + (unsigned)(((warp_m*16 + ar)*PA + ks*16 + ac)*2));
        #pragma unroll
        for (int nb = 0; nb < 2; nb++)
            ldsm_x4(b[nb], Bsu + (unsigned)(((warp_n*32 + nb*16 + bj)*PB + ks*16 + bk2)*2));
        #pragma unroll
        for (int nb = 0; nb < 2; nb++){
            mma16816(d[nb*2+0], a, &b[nb][0]);
            mma16816(d[nb*2+1], a, &b[nb][2]);
        }
    }
}

// ---------------------------------------------------------------------------
// Kernel 1: A/B precompute (GEMM, fp32 SIMT) -> fp16 g_ABh (A+b1), g_Bh
// ---------------------------------------------------------------------------
__global__ void k_pre(const float* __restrict__ nf, const float* __restrict__ w1,
                      const float* __restrict__ b1)
{
    __shared__ float As[16][64];
    __shared__ float Bs[16][64];
    int tid = threadIdx.x;
    int m0 = blockIdx.y*64, h0 = blockIdx.x*64;
    int tx = tid & 15, ty = tid >> 4;
    float acc[4][4] = {};
    for (int k0 = 0; k0 < D_; k0 += 16){
        #pragma unroll
        for (int i = 0; i < 4; i++){
            int e = i*256 + tid;
            int r = e >> 4, kk = e & 15;
            As[kk][r] = nf[(m0 + r)*D_ + k0 + kk];
        }
        {
            int o  = tid >> 2;
            int kq = (tid & 3)*4;
            int hp = h0 + o;
            const float* src = w1 + (hp & 255)*(2*D_) + (hp >> 8)*D_ + k0 + kq;
            float4 w = *(const float4*)src;
            Bs[kq+0][o] = w.x; Bs[kq+1][o] = w.y; Bs[kq+2][o] = w.z; Bs[kq+3][o] = w.w;
        }
        __syncthreads();
        #pragma unroll
        for (int kk = 0; kk < 16; kk++){
            float ra[4], rb[4];
            #pragma unroll
            for (int i = 0; i < 4; i++) ra[i] = As[kk][ty*4 + i];
            #pragma unroll
            for (int jj = 0; jj < 4; jj++) rb[jj] = Bs[kk][tx*4 + jj];
            #pragma unroll
            for (int i = 0; i < 4; i++)
                #pragma unroll
                for (int jj = 0; jj < 4; jj++)
                    acc[i][jj] += ra[i]*rb[jj];
        }
        __syncthreads();
    }
    #pragma unroll
    for (int i = 0; i < 4; i++)
        #pragma unroll
        for (int jj = 0; jj < 4; jj++){
            int hp = h0 + tx*4 + jj;
            int row = m0 + ty*4 + i;
            float v = acc[i][jj];
            if (hp < H0_) g_ABh[row*H0_ + hp]         = __float2half_rn(v + b1[hp]);
            else          g_Bh [row*H0_ + (hp - 256)] = __float2half_rn(v);
        }
}

// ---------------------------------------------------------------------------
// Kernel 1b: W2 -> fp16 once
// ---------------------------------------------------------------------------
__global__ void k_w2h(const float* __restrict__ w2)
{
    int i = blockIdx.x*256 + threadIdx.x;
    if (i < H1_*H0_) g_W2h[i] = __float2half_rn(w2[i]);
}

// ---------------------------------------------------------------------------
// Kernel 2: pairwise MLP; 2 'a' rows per block sharing the staged raw B tile.
// ---------------------------------------------------------------------------
__global__ void __launch_bounds__(256, 1)
k_pair(const float* __restrict__ b2v, const float* __restrict__ w3,
       const float* __restrict__ b3v, float* __restrict__ score_out)
{
    extern __shared__ char smraw[];
    __half* h1s = (__half*)smraw;                 // 128*ROWH
    __half* W2s = h1s + 128*ROWH;                 // 128*ROWH
    __half* rBs = W2s + 128*ROWH;                 // 128*ROWH (raw B tile)
    __half* Ar0 = rBs + 128*ROWH;                 // 256
    __half* Ar1 = Ar0 + H0_;                      // 256
    float*  sred = (float*)(Ar1 + H0_);           // 128
    float*  b2s  = sred + H1_;                    // 128
    float*  w3s  = b2s + H1_;                     // 128

    int a0 = blockIdx.x*2, a1 = a0 + 1;
    int t  = a0 / N_;
    int tid = threadIdx.x, lane = tid & 31, wid = tid >> 5;
    int warp_n = wid & 3, warp_m = wid >> 2;

    // stage W2 (fp16 copy), A rows, biases
    #pragma unroll
    for (int i = 0; i < 16; i++){
        int idx = i*256 + tid;
        int row = idx >> 5, c8 = idx & 31;
        *(uint4*)&W2s[row*ROWH + c8*8] = *(const uint4*)&g_W2h[row*H0_ + c8*8];
    }
    Ar0[tid] = g_ABh[a0*H0_ + tid];
    Ar1[tid] = g_ABh[a1*H0_ + tid];
    if (tid < H1_){ b2s[tid] = b2v[tid]; w3s[tid] = w3[tid]; }
    float b3 = b3v[0];

    unsigned h1u = (unsigned)__cvta_generic_to_shared(h1s);
    unsigned w2u = (unsigned)__cvta_generic_to_shared(W2s);

    int a_trow  = lane & 15;
    int a_tcol8 = (lane >> 4) * 8;
    int b_g     = lane >> 3;
    int b_joff  = ((b_g >= 2) ? 8 : 0) + (lane & 7);
    int b_koff  = (b_g & 1) * 8;

    unsigned aA[4], bA[2];
    #pragma unroll
    for (int mt = 0; mt < 4; mt++)
        aA[mt] = h1u + ((warp_m*64 + mt*16 + a_trow)*ROWH + a_tcol8)*2;
    #pragma unroll
    for (int nb = 0; nb < 2; nb++)
        bA[nb] = w2u + ((warp_n*32 + nb*16 + b_joff)*ROWH + b_koff)*2;

    const __half2 z2 = __float2half2_rn(0.f);

    for (int b0 = 0; b0 < N_; b0 += 128){
        __syncthreads();
        // stage raw B + h1 for a0
        #pragma unroll
        for (int i = 0; i < 16; i++){
            int idx = i*256 + tid;
            int row = idx >> 5, c8 = idx & 31;
            int bg = b0 + row;
            uint4 v = make_uint4(0u,0u,0u,0u);
            if (bg < N_) v = *(const uint4*)&g_Bh[((size_t)(t*N_ + bg))*H0_ + c8*8];
            *(uint4*)&rBs[row*ROWH + c8*8] = v;
            const __half2* vp = (const __half2*)&v;
            uint4 o;
            __half2* op = (__half2*)&o;
            #pragma unroll
            for (int q = 0; q < 4; q++)
                op[q] = __hmax2(__hadd2(vp[q], *(const __half2*)&Ar0[c8*8 + q*2]), z2);
            *(uint4*)&h1s[row*ROWH + c8*8] = o;
        }
        if (tid < H1_) sred[tid] = 0.f;
        __syncthreads();

        // ---- GEMM + epilogue for a0 ----
        {
            float d[4][4][4];
            #pragma unroll
            for (int i=0;i<4;i++)
                #pragma unroll
                for (int j=0;j<4;j++)
                    #pragma unroll
                    for (int v=0;v<4;v++) d[i][j][v]=0.f;
            for (int ks = 0; ks < 16; ks++){
                unsigned a[4][4], b[2][4];
                #pragma unroll
                for (int mt = 0; mt < 4; mt++) ldsm_x4(a[mt], aA[mt] + ks*32);
                #pragma unroll
                for (int nb = 0; nb < 2; nb++) ldsm_x4(b[nb], bA[nb] + ks*32);
                #pragma unroll
                for (int mt = 0; mt < 4; mt++)
                    #pragma unroll
                    for (int nb = 0; nb < 2; nb++){
                        mma16816(d[mt][nb*2+0], a[mt], &b[nb][0]);
                        mma16816(d[mt][nb*2+1], a[mt], &b[nb][2]);
                    }
            }
            #pragma unroll
            for (int mt = 0; mt < 4; mt++){
                #pragma unroll
                for (int h = 0; h < 2; h++){
                    float part = 0.f;
                    #pragma unroll
                    for (int n8 = 0; n8 < 4; n8++){
                        #pragma unroll
                        for (int c = 0; c < 2; c++){
                            int j = warp_n*32 + n8*8 + (lane & 3)*2 + c;
                            part += fmaxf(d[mt][n8][h*2 + c] + b2s[j], 0.f) * w3s[j];
                        }
                    }
                    part += __shfl_xor_sync(0xffffffff, part, 1);
                    part += __shfl_xor_sync(0xffffffff, part, 2);
                    if ((lane & 3) == 0)
                        atomicAdd(&sred[warp_m*64 + mt*16 + (lane >> 2) + h*8], part);
                }
            }
        }
        __syncthreads();
        if (tid < H1_){
            int bg = b0 + tid;
            if (bg < N_) score_out[a0*N_ + bg] = sigmoidf_(sred[tid] + b3);
            sred[tid] = 0.f;
        }
        // stage h1 for a1 from rBs (smem only)
        #pragma unroll
        for (int i = 0; i < 16; i++){
            int idx = i*256 + tid;
            int row = idx >> 5, c8 = idx & 31;
            uint4 v = *(const uint4*)&rBs[row*ROWH + c8*8];
            const __half2* vp = (const __half2*)&v;
            uint4 o;
            __half2* op = (__half2*)&o;
            #pragma unroll
            for (int q = 0; q < 4; q++)
                op[q] = __hmax2(__hadd2(vp[q], *(const __half2*)&Ar1[c8*8 + q*2]), z2);
            *(uint4*)&h1s[row*ROWH + c8*8] = o;
        }
        __syncthreads();

        // ---- GEMM + epilogue for a1 ----
        {
            float d[4][4][4];
            #pragma unroll
            for (int i=0;i<4;i++)
                #pragma unroll
                for (int j=0;j<4;j++)
                    #pragma unroll
                    for (int v=0;v<4;v++) d[i][j][v]=0.f;
            for (int ks = 0; ks < 16; ks++){
                unsigned a[4][4], b[2][4];
                #pragma unroll
                for (int mt = 0; mt < 4; mt++) ldsm_x4(a[mt], aA[mt] + ks*32);
                #pragma unroll
                for (int nb = 0; nb < 2; nb++) ldsm_x4(b[nb], bA[nb] + ks*32);
                #pragma unroll
                for (int mt = 0; mt < 4; mt++)
                    #pragma unroll
                    for (int nb = 0; nb < 2; nb++){
                        mma16816(d[mt][nb*2+0], a[mt], &b[nb][0]);
                        mma16816(d[mt][nb*2+1], a[mt], &b[nb][2]);
                    }
            }
            #pragma unroll
            for (int mt = 0; mt < 4; mt++){
                #pragma unroll
                for (int h = 0; h < 2; h++){
                    float part = 0.f;
                    #pragma unroll
                    for (int n8 = 0; n8 < 4; n8++){
                        #pragma unroll
                        for (int c = 0; c < 2; c++){
                            int j = warp_n*32 + n8*8 + (lane & 3)*2 + c;
                            part += fmaxf(d[mt][n8][h*2 + c] + b2s[j], 0.f) * w3s[j];
                        }
                    }
                    part += __shfl_xor_sync(0xffffffff, part, 1);
                    part += __shfl_xor_sync(0xffffffff, part, 2);
                    if ((lane & 3) == 0)
                        atomicAdd(&sred[warp_m*64 + mt*16 + (lane >> 2) + h*8], part);
                }
            }
        }
        __syncthreads();
        if (tid < H1_){
            int bg = b0 + tid;
            if (bg < N_) score_out[a1*N_ + bg] = sigmoidf_(sred[tid] + b3);
        }
    }
}

// ---------------------------------------------------------------------------
// Kernel 2b: learned_adj -> fp16 (removes gather/mask from k_wl's hot loop)
// ---------------------------------------------------------------------------
__global__ void k_ladj(const float* __restrict__ adj, const float* __restrict__ score)
{
    int idx = blockIdx.x*256 + threadIdx.x;
    if (idx >= T_*N_*N_) return;
    int t = idx / (N_*N_);
    int r = idx % (N_*N_);
    int n = r / N_, m = r % N_;
    float v = score[idx];
    if (n < S_ && m < S_)
        v = (adj[(t*S_ + n)*S_ + m] > 0.f) ? 1.f : -v;
    g_ladjH[idx] = __float2half_rn(v);
}

// ---------------------------------------------------------------------------
// Kernel 3: support (hi/lo split, 3 passes), 64x64 tiles
// ---------------------------------------------------------------------------
__global__ void __launch_bounds__(256)
k_support(const float* __restrict__ nf, const float* __restrict__ Wg)
{
    __shared__ __align__(16) __half Ah[64*72];
    __shared__ __align__(16) __half Al[64*72];
    __shared__ __align__(16) __half Bh[64*72];
    __shared__ __align__(16) __half Bl[64*72];
    int tid = threadIdx.x, lane = tid & 31, wid = tid >> 5;
    int warp_m = wid >> 1, warp_n = wid & 1;
    int o0 = blockIdx.x*64, m0 = blockIdx.y*64;
    unsigned Ahu = (unsigned)__cvta_generic_to_shared(Ah);
    unsigned Alu = (unsigned)__cvta_generic_to_shared(Al);
    unsigned Bhu = (unsigned)__cvta_generic_to_shared(Bh);
    unsigned Blu = (unsigned)__cvta_generic_to_shared(Bl);
    float d[4][4] = {};

    for (int k0 = 0; k0 < GD_; k0 += 64){
        #pragma unroll
        for (int i = 0; i < 4; i++){
            int idx = i*256 + tid;
            int row = idx >> 4, c4 = idx & 15;
            int m = m0 + row, f = k0 + c4*4;
            float4 v = make_float4(0.f,0.f,0.f,0.f);
            if (m < TNROWS){
                int tt = m / N_, n = m % N_;
                int node = (f < D_) ? n : (S_ + (f >> 7) - 1);
                v = *(const float4*)&nf[(tt*N_ + node)*D_ + (f & 127)];
            }
            __half h0,l0,h1,l1,h2,l2,h3,l3;
            split2(v.x,h0,l0); split2(v.y,h1,l1); split2(v.z,h2,l2); split2(v.w,h3,l3);
            *(__half2*)&Ah[row*72 + c4*4]     = __halves2half2(h0,h1);
            *(__half2*)&Ah[row*72 + c4*4 + 2] = __halves2half2(h2,h3);
            *(__half2*)&Al[row*72 + c4*4]     = __halves2half2(l0,l1);
            *(__half2*)&Al[row*72 + c4*4 + 2] = __halves2half2(l2,l3);
        }
        #pragma unroll
        for (int i = 0; i < 4; i++){
            int idx = i*256 + tid;
            int row = idx >> 4, c4 = idx & 15;
            float4 v = *(const float4*)&Wg[(k0 + row)*GD_ + o0 + c4*4];
            __half h0,l0,h1,l1,h2,l2,h3,l3;
            split2(v.x,h0,l0); split2(v.y,h1,l1); split2(v.z,h2,l2); split2(v.w,h3,l3);
            *(__half2*)&Bh[row*72 + c4*4]     = __halves2half2(h0,h1);
            *(__half2*)&Bh[row*72 + c4*4 + 2] = __halves2half2(h2,h3);
            *(__half2*)&Bl[row*72 + c4*4]     = __halves2half2(l0,l1);
            *(__half2*)&Bl[row*72 + c4*4 + 2] = __halves2half2(l2,l3);
        }
        __syncthreads();
        mma_m16n32_t(d, Ahu, Bhu, lane, warp_m, warp_n, 72, 72);
        mma_m16n32_t(d, Ahu, Blu, lane, warp_m, warp_n, 72, 72);
        mma_m16n32_t(d, Alu, Bhu, lane, warp_m, warp_n, 72, 72);
        __syncthreads();
    }
    #pragma unroll
    for (int n8 = 0; n8 < 4; n8++)
        #pragma unroll
        for (int v = 0; v < 4; v++){
            int row = m0 + warp_m*16 + (lane >> 2) + (v >> 1)*8;
            int col = o0 + warp_n*32 + n8*8 + (lane & 3)*2 + (v & 1);
            if (row < TNROWS){
                __half h, l;
                split2(d[n8][v], h, l);
                g_supH[row*GD_ + col] = h;
                g_supL[row*GD_ + col] = l;
            }
        }
}

// ---------------------------------------------------------------------------
// Kernel 4: wl = relu(ladj·sup + biasG), 64x64 tiles, B hi+lo (2 passes)
// ---------------------------------------------------------------------------
__global__ void __launch_bounds__(256)
k_wl(const float* __restrict__ biasG)
{
    __shared__ __align__(16) __half As[64*72];
    __shared__ __align__(16) __half Bh[64*72];
    __shared__ __align__(16) __half Bl[64*72];
    int tid = threadIdx.x, lane = tid & 31, wid = tid >> 5;
    int warp_m = wid >> 1, warp_n = wid & 1;
    int o0 = blockIdx.x*64, m0 = blockIdx.y*64, t = blockIdx.z;
    unsigned Asu = (unsigned)__cvta_generic_to_shared(As);
    unsigned Bhu = (unsigned)__cvta_generic_to_shared(Bh);
    unsigned Blu = (unsigned)__cvta_generic_to_shared(Bl);
    float d[4][4] = {};

    for (int k0 = 0; k0 < N_; k0 += 64){
        #pragma unroll
        for (int i = 0; i < 2; i++){
            int idx = i*256 + tid;
            int row = idx >> 3, c8 = idx & 7;
            int n = m0 + row, k = k0 + c8*8;
            uint4 v = make_uint4(0u,0u,0u,0u);
            if (n < N_ && k < N_)
                v = *(const uint4*)&g_ladjH[(t*N_ + n)*N_ + k];
            *(uint4*)&As[row*72 + c8*8] = v;
        }
        #pragma unroll
        for (int i = 0; i < 2; i++){
            int idx = i*256 + tid;
            int row = idx >> 3, c8 = idx & 7;
            int k = k0 + row;
            uint4 vh = make_uint4(0u,0u,0u,0u);
            uint4 vl = make_uint4(0u,0u,0u,0u);
            if (k < N_){
                vh = *(const uint4*)&g_supH[(t*N_ + k)*GD_ + o0 + c8*8];
                vl = *(const uint4*)&g_supL[(t*N_ + k)*GD_ + o0 + c8*8];
            }
            *(uint4*)&Bh[row*72 + c8*8] = vh;
            *(uint4*)&Bl[row*72 + c8*8] = vl;
        }
        __syncthreads();
        mma_m16n32_t(d, Asu, Bhu, lane, warp_m, warp_n, 72, 72);
        mma_m16n32_t(d, Asu, Blu, lane, warp_m, warp_n, 72, 72);
        __syncthreads();
    }
    #pragma unroll
    for (int n8 = 0; n8 < 4; n8++)
        #pragma unroll
        for (int v = 0; v < 4; v++){
            int n = m0 + warp_m*16 + (lane >> 2) + (v >> 1)*8;
            int o = o0 + warp_n*32 + n8*8 + (lane & 3)*2 + (v & 1);
            if (n < N_)
                g_wl[(t*N_ + n)*GD_ + o] = fmaxf(d[n8][v] + biasG[o], 0.f);
        }
}

// ---------------------------------------------------------------------------
// Kernel 5: wl mean over t -> out[0 .. 307200)
// ---------------------------------------------------------------------------
__global__ void k_mean(float* __restrict__ out)
{
    int i = blockIdx.x*blockDim.x + threadIdx.x;
    if (i < N_*GD_){
        float s = g_wl[i] + g_wl[i + N_*GD_] + g_wl[i + 2*N_*GD_] + g_wl[i + 3*N_*GD_];
        out[i] = 0.25f * s;
    }
}

// ---------------------------------------------------------------------------
// Kernel 6: h2a = relu(wl·W1^T + b1), hi/lo split MMA (3 passes), 64x64 tiles
// ---------------------------------------------------------------------------
__global__ void __launch_bounds__(256)
k_fc2a(const float* __restrict__ W, const float* __restrict__ bias)
{
    __shared__ __align__(16) __half Ah[64*72];
    __shared__ __align__(16) __half Al[64*72];
    __shared__ __align__(16) __half Bh[64*72];
    __shared__ __align__(16) __half Bl[64*72];
    int tid = threadIdx.x, lane = tid & 31, wid = tid >> 5;
    int warp_m = wid >> 1, warp_n = wid & 1;
    int o0 = blockIdx.x*64, m0 = blockIdx.y*64;
    unsigned Ahu = (unsigned)__cvta_generic_to_shared(Ah);
    unsigned Alu = (unsigned)__cvta_generic_to_shared(Al);
    unsigned Bhu = (unsigned)__cvta_generic_to_shared(Bh);
    unsigned Blu = (unsigned)__cvta_generic_to_shared(Bl);
    float d[4][4] = {};

    for (int k0 = 0; k0 < GD_; k0 += 64){
        #pragma unroll
        for (int i = 0; i < 4; i++){
            int idx = i*256 + tid;
            int row = idx >> 4, c4 = idx & 15;
            int m = m0 + row;
            float4 v = make_float4(0.f,0.f,0.f,0.f);
            if (m < TNROWS) v = *(const float4*)&g_wl[m*GD_ + k0 + c4*4];
            __half h0,l0,h1,l1,h2,l2,h3,l3;
            split2(v.x,h0,l0); split2(v.y,h1,l1); split2(v.z,h2,l2); split2(v.w,h3,l3);
            *(__half2*)&Ah[row*72 + c4*4]     = __halves2half2(h0,h1);
            *(__half2*)&Ah[row*72 + c4*4 + 2] = __halves2half2(h2,h3);
            *(__half2*)&Al[row*72 + c4*4]     = __halves2half2(l0,l1);
            *(__half2*)&Al[row*72 + c4*4 + 2] = __halves2half2(l2,l3);
        }
        #pragma unroll
        for (int i = 0; i < 4; i++){
            int idx = i*256 + tid;
            int row = idx >> 4, c4 = idx & 15;      // row = j (output neuron)
            float4 v = *(const float4*)&W[(o0 + row)*GD_ + k0 + c4*4];
            __half h0,l0,h1,l1,h2,l2,h3,l3;
            split2(v.x,h0,l0); split2(v.y,h1,l1); split2(v.z,h2,l2); split2(v.w,h3,l3);
            *(__half2*)&Bh[row*72 + c4*4]     = __halves2half2(h0,h1);
            *(__half2*)&Bh[row*72 + c4*4 + 2] = __halves2half2(h2,h3);
            *(__half2*)&Bl[row*72 + c4*4]     = __halves2half2(l0,l1);
            *(__half2*)&Bl[row*72 + c4*4 + 2] = __halves2half2(l2,l3);
        }
        __syncthreads();
        mma_m16n32_n(d, Ahu, Bhu, lane, warp_m, warp_n, 72, 72);
        mma_m16n32_n(d, Ahu, Blu, lane, warp_m, warp_n, 72, 72);
        mma_m16n32_n(d, Alu, Bhu, lane, warp_m, warp_n, 72, 72);
        __syncthreads();
    }
    #pragma unroll
    for (int n8 = 0; n8 < 4; n8++)
        #pragma unroll
        for (int v = 0; v < 4; v++){
            int row = m0 + warp_m*16 + (lane >> 2) + (v >> 1)*8;
            int col = o0 + warp_n*32 + n8*8 + (lane & 3)*2 + (v & 1);
            if (row < TNROWS)
                g_h2a[row*H1_ + col] = fmaxf(d[n8][v] + bias[col], 0.f);
        }
}

// ---------------------------------------------------------------------------
// Kernel 7: h2b = relu(h2a·W2^T + b)  fp32 SIMT  M=1600,K=128,O=128
// ---------------------------------------------------------------------------
__global__ void k_fc2b(const float* __restrict__ W, const float* __restrict__ bias)
{
    __shared__ float As[16][64];
    __shared__ float Bs[16][64];
    int tid = threadIdx.x;
    int m0 = blockIdx.y*64, o0 = blockIdx.x*64;
    int tx = tid & 15, ty = tid >> 4;
    float acc[4][4] = {};
    for (int k0 = 0; k0 < H1_; k0 += 16){
        #pragma unroll
        for (int i = 0; i < 4; i++){
            int e = i*256 + tid;
            int r = e >> 4, kk = e & 15;
            As[kk][r] = g_h2a[(m0 + r)*H1_ + k0 + kk];
        }
        {
            int o  = tid >> 2;
            int kq = (tid & 3)*4;
            float4 w = *(const float4*)&W[(o0 + o)*H1_ + k0 + kq];
            Bs[kq+0][o] = w.x; Bs[kq+1][o] = w.y; Bs[kq+2][o] = w.z; Bs[kq+3][o] = w.w;
        }
        __syncthreads();
        #pragma unroll
        for (int kk = 0; kk < 16; kk++){
            float ra[4], rb[4];
            #pragma unroll
            for (int i = 0; i < 4; i++) ra[i] = As[kk][ty*4 + i];
            #pragma unroll
            for (int jj = 0; jj < 4; jj++) rb[jj] = Bs[kk][tx*4 + jj];
            #pragma unroll
            for (int i = 0; i < 4; i++)
                #pragma unroll
                for (int jj = 0; jj < 4; jj++)
                    acc[i][jj] += ra[i]*rb[jj];
        }
        __syncthreads();
    }
    #pragma unroll
    for (int i = 0; i < 4; i++)
        #pragma unroll
        for (int jj = 0; jj < 4; jj++){
            int o = o0 + tx*4 + jj;
            g_h2b[(m0 + ty*4 + i)*H1_ + o] = fmaxf(acc[i][jj] + bias[o], 0.f);
        }
}

// ---------------------------------------------------------------------------
// Kernel 8: query[t,c,n] = sigmoid( h2b[t,n,:]·w3[c,:] + b3[c] )
// ---------------------------------------------------------------------------
__global__ void k_query(const float* __restrict__ w3, const float* __restrict__ b3,
                        float* __restrict__ out)
{
    int idx = blockIdx.x*blockDim.x + threadIdx.x;
    if (idx >= TNROWS*5) return;
    int row = idx / 5, c = idx % 5;
    const float* h = g_h2b + row*H1_;
    const float* w = w3 + c*H1_;
    float s = 0.f;
    #pragma unroll 8
    for (int k = 0; k < H1_; k++) s += h[k]*w[k];
    int t = row / N_, n = row % N_;
    out[OUT_QS + t*5*N_ + c*N_ + n] = sigmoidf_(s + b3[c]);
}

// ---------------------------------------------------------------------------
extern "C" void kernel_launch(void* const* d_in, const int* in_sizes, int n_in,
                              void* d_out, int out_size)
{
    const float* nf       = (const float*)d_in[0];
    const float* adj      = (const float*)d_in[1];
    const float* fc1_w1   = (const float*)d_in[2];
    const float* fc1_b1   = (const float*)d_in[3];
    const float* fc1_w2   = (const float*)d_in[4];
    const float* fc1_b2   = (const float*)d_in[5];
    const float* fc1_w3   = (const float*)d_in[6];
    const float* fc1_b3   = (const float*)d_in[7];
    const float* weight_G = (const float*)d_in[8];
    const float* bias_G   = (const float*)d_in[9];
    const float* fc2_w1   = (const float*)d_in[10];
    const float* fc2_b1   = (const float*)d_in[11];
    const float* fc2_w2   = (const float*)d_in[12];
    const float* fc2_b2   = (const float*)d_in[13];
    const float* fc2_w3   = (const float*)d_in[14];
    const float* fc2_b3   = (const float*)d_in[15];

    float* out       = (float*)d_out;
    float* score_out = out + OUT_SCORE;

    size_t smem_pair = (size_t)(3*128*ROWH + 2*H0_)*sizeof(__half)
                     + (size_t)(3*H1_)*sizeof(float);
    cudaFuncSetAttribute(k_pair, cudaFuncAttributeMaxDynamicSharedMemorySize, (int)smem_pair);

    k_pre<<<dim3(8, 25), 256>>>(nf, fc1_w1, fc1_b1);
    k_w2h<<<(H1_*H0_ + 255)/256, 256>>>(fc1_w2);
    k_pair<<<TNROWS/2, 256, smem_pair>>>(fc1_b2, fc1_w3, fc1_b3, score_out);
    k_ladj<<<(T_*N_*N_ + 255)/256, 256>>>(adj, score_out);
    k_support<<<dim3(GD_/64, (TNROWS + 63)/64), 256>>>(nf, weight_G);
    k_wl<<<dim3(GD_/64, (N_ + 63)/64, T_), 256>>>(bias_G);
    k_mean<<<(N_*GD_ + 255)/256, 256>>>(out);
    k_fc2a<<<dim3(H1_/64, (TNROWS + 63)/64), 256>>>(fc2_w1, fc2_b1);
    k_fc2b<<<dim3(H1_/64, TNROWS/64), 256>>>(fc2_w2, fc2_b2);
    k_query<<<(TNROWS*5 + 127)/128, 128>>>(fc2_w3, fc2_b3, out);
}